// round 2
// baseline (speedup 1.0000x reference)
#include <cuda_runtime.h>
#include <cfloat>

#define B_ 2
#define N_ 8192
#define M_ 4096
#define C_ 64
#define HID_ 256
#define KNN_ 15
#define P_ (B_*N_)

// ---------------- scratch (no allocations allowed) ----------------
__device__ float g_v[B_*M_*HID_];        // 8 MB : W2a'[:, :3] . pcl[m]
__device__ float g_R[(size_t)P_*HID_];   // 16 MB: weighted relu sums
__device__ float g_DF[(size_t)P_*192];   // 12 MB: [close_feat | co_feat | point_feat]
__device__ float g_sw[P_];               // sum of weights per point
__device__ int   g_close[P_];            // nearest clean index per noisy point
__device__ int   g_knn[B_*M_*KNN_];      // 15-NN (self excluded) per clean point
__device__ float g_w2as[HID_*6];         // BN-folded W2a
__device__ float g_b2as[HID_];
__device__ float g_w2bT[HID_*C_];        // W2b transposed [k][o]
__device__ float g_w1asT[192*C_];        // BN-folded W1a transposed [k][o]
__device__ float g_b1as[C_];
__device__ float g_w1bT[C_*C_];          // W1b transposed [k][o]

// ---------------- weight prep: fold BN scale, transpose ----------------
__global__ void k_prep(const float* __restrict__ w2a, const float* __restrict__ b2a,
                       const float* __restrict__ g2a, const float* __restrict__ bt2a,
                       const float* __restrict__ w2b, const float* __restrict__ w1a,
                       const float* __restrict__ b1a, const float* __restrict__ g1a,
                       const float* __restrict__ bt1a, const float* __restrict__ w1b) {
    int t = threadIdx.x;
    const float sc = rsqrtf(1.0f + 1e-5f);
    if (t < HID_) {
        float s = g2a[t] * sc;
        #pragma unroll
        for (int d = 0; d < 6; d++) g_w2as[t*6+d] = w2a[t*6+d] * s;
        g_b2as[t] = b2a[t] * s + bt2a[t];
    }
    if (t < C_) {
        float s = g1a[t] * sc;
        for (int j = 0; j < 192; j++) g_w1asT[j*C_+t] = w1a[t*192+j] * s;
        g_b1as[t] = b1a[t] * s + bt1a[t];
    }
    for (int i = t; i < HID_*C_; i += 256) { int j = i >> 6, o = i & 63; g_w2bT[i] = w2b[o*HID_+j]; }
    for (int i = t; i < C_*C_;  i += 256) { int j = i >> 6, o = i & 63; g_w1bT[i] = w1b[o*C_+j]; }
}

// ---------------- v table: v[b,m,c] = W2a'[c,0:3] . pcl[b,m] ----------------
__global__ void k_vtab(const float* __restrict__ pcl) {
    int idx = blockIdx.x * blockDim.x + threadIdx.x;   // B*M*HID threads
    if (idx >= B_*M_*HID_) return;
    int pm = idx >> 8, c = idx & 255;
    float x = pcl[pm*3], y = pcl[pm*3+1], z = pcl[pm*3+2];
    g_v[idx] = g_w2as[c*6]*x + g_w2as[c*6+1]*y + g_w2as[c*6+2]*z;
}

// ---------------- nearest clean point per noisy point ----------------
#define CT_ 2048
__global__ void __launch_bounds__(256) k_close(const float* __restrict__ pcl,
                                               const float* __restrict__ noise) {
    __shared__ float sx[CT_], sy[CT_], sz[CT_];
    __shared__ float rb[8][32];
    __shared__ int   ri[8][32];
    int blk = blockIdx.x;                 // 512 blocks: 256 per batch
    int b   = blk >> 8;
    int pt  = threadIdx.x & 31;
    int s   = threadIdx.x >> 5;           // 8-way split of M
    int n   = (blk & 255) * 32 + pt;
    const float* PB = pcl + b*M_*3;
    float nx = noise[(b*N_+n)*3+0], ny = noise[(b*N_+n)*3+1], nz = noise[(b*N_+n)*3+2];
    float best = FLT_MAX; int bi = 0;
    for (int t0 = 0; t0 < M_; t0 += CT_) {
        for (int i = threadIdx.x; i < CT_; i += 256) {
            sx[i] = PB[(t0+i)*3]; sy[i] = PB[(t0+i)*3+1]; sz[i] = PB[(t0+i)*3+2];
        }
        __syncthreads();
        int lo = s * (CT_/8), hi = lo + CT_/8;
        for (int i = lo; i < hi; i++) {
            float dx = sx[i]-nx, dy = sy[i]-ny, dz = sz[i]-nz;
            float d  = fmaf(dx, dx, fmaf(dy, dy, dz*dz));
            if (d < best) { best = d; bi = t0 + i; }
        }
        __syncthreads();
    }
    rb[s][pt] = best; ri[s][pt] = bi;
    __syncthreads();
    if (s == 0) {
        #pragma unroll
        for (int ss = 1; ss < 8; ss++) {
            float d = rb[ss][pt];
            if (d < best) { best = d; bi = ri[ss][pt]; }
        }
        g_close[b*N_+n] = bi;
    }
}

// ---------------- 15-NN (self excluded) per clean point: warp/point ----------------
#define KT_ 1024
__global__ void __launch_bounds__(256) k_knn(const float* __restrict__ pcl) {
    __shared__ float sx[KT_], sy[KT_], sz[KT_];
    __shared__ float sd[8][32][KNN_];
    __shared__ int   si[8][32][KNN_];
    int blk  = blockIdx.x;                // 1024 blocks: 512 per batch, 8 points each
    int b    = blk >> 9;
    int w    = threadIdx.x >> 5;
    int lane = threadIdx.x & 31;
    int m    = (blk & 511) * 8 + w;
    const float* PB = pcl + b*M_*3;
    float qx = PB[m*3], qy = PB[m*3+1], qz = PB[m*3+2];
    float* D = sd[w][lane];
    int*   I = si[w][lane];
    #pragma unroll
    for (int j = 0; j < KNN_; j++) { D[j] = FLT_MAX; I[j] = -1; }
    float worst = FLT_MAX;
    for (int t0 = 0; t0 < M_; t0 += KT_) {
        for (int i = threadIdx.x; i < KT_; i += 256) {
            sx[i] = PB[(t0+i)*3]; sy[i] = PB[(t0+i)*3+1]; sz[i] = PB[(t0+i)*3+2];
        }
        __syncthreads();
        for (int i = lane; i < KT_; i += 32) {
            int c = t0 + i;
            float dx = sx[i]-qx, dy = sy[i]-qy, dz = sz[i]-qz;
            float d  = fmaf(dx, dx, fmaf(dy, dy, dz*dz));
            if (d < worst && c != m) {
                int j = KNN_ - 1;
                #pragma unroll 1
                while (j > 0 && D[j-1] > d) { D[j] = D[j-1]; I[j] = I[j-1]; j--; }
                D[j] = d; I[j] = c;
                worst = D[KNN_-1];
            }
        }
        __syncthreads();
    }
    // merge 32 per-lane sorted lists via 15 rounds of warp arg-min
    int ptr = 0; float v = D[0]; int vi = I[0];
    int* dst = g_knn + (b*M_+m)*KNN_;
    for (int r = 0; r < KNN_; r++) {
        float bd = v; int bidx = vi; int blane = lane;
        #pragma unroll
        for (int off = 16; off > 0; off >>= 1) {
            float od = __shfl_down_sync(0xffffffffu, bd, off);
            int   oi = __shfl_down_sync(0xffffffffu, bidx, off);
            int   ol = __shfl_down_sync(0xffffffffu, blane, off);
            if (od < bd) { bd = od; bidx = oi; blane = ol; }
        }
        bidx  = __shfl_sync(0xffffffffu, bidx, 0);
        blane = __shfl_sync(0xffffffffu, blane, 0);
        if (lane == 0) dst[r] = bidx;
        if (lane == blane) {
            ptr++;
            if (ptr < KNN_) { v = D[ptr]; vi = I[ptr]; } else { v = FLT_MAX; vi = -1; }
        }
    }
}

// ---------------- assemble: weights, weighted relu sums R, df[0:128] ----------------
__global__ void __launch_bounds__(256) k_assemble(const float* __restrict__ pcl,
                                                  const float* __restrict__ noise,
                                                  const float* __restrict__ feature) {
    int w = threadIdx.x >> 5, lane = threadIdx.x & 31;
    int p = blockIdx.x * 8 + w;           // warp per noisy point
    int b = p >> 13;                      // N = 8192
    int m0 = g_close[p];
    const float* PB = pcl + b*M_*3;
    const float* FB = feature + b*M_*C_;
    float nx = noise[p*3], ny = noise[p*3+1], nz = noise[p*3+2];
    float cx = PB[m0*3], cy = PB[m0*3+1], cz = PB[m0*3+2];
    float t[8], r[8];
    #pragma unroll
    for (int j = 0; j < 8; j++) {
        int c = lane + 32*j;
        const float* wv = g_w2as + c*6;
        t[j] = g_b2as[c] + wv[3]*cx + wv[4]*cy + wv[5]*cz
                         - (wv[0]*nx + wv[1]*ny + wv[2]*nz);
        r[j] = 0.f;
    }
    float S = 0.f, co0 = 0.f, co1 = 0.f;
    const int* nbp = g_knn + (b*M_+m0)*KNN_;
    #pragma unroll 1
    for (int k = 0; k < KNN_; k++) {
        int nb = nbp[k];
        float dx = PB[nb*3]-nx, dy = PB[nb*3+1]-ny, dz = PB[nb*3+2]-nz;
        float dst = sqrtf(fmaf(dx, dx, fmaf(dy, dy, dz*dz)));
        float e = __expf(-10.f * dst);
        S += e;
        const float* vr = g_v + (nb + b*M_)*HID_;
        #pragma unroll
        for (int j = 0; j < 8; j++) {
            float h = vr[lane + 32*j] + t[j];
            r[j] = fmaf(e, fmaxf(h, 0.f), r[j]);
        }
        co0 = fmaf(e, FB[nb*C_+lane],    co0);
        co1 = fmaf(e, FB[nb*C_+32+lane], co1);
    }
    float inv = 1.f / (S + 1e-7f);
    float* Rr = g_R + (size_t)p*HID_;
    #pragma unroll
    for (int j = 0; j < 8; j++) Rr[lane + 32*j] = r[j] * inv;
    float* dfp = g_DF + (size_t)p*192;
    dfp[lane]       = FB[m0*C_+lane];
    dfp[32+lane]    = FB[m0*C_+32+lane];
    dfp[64+lane]    = co0 * inv;
    dfp[96+lane]    = co1 * inv;
    if (lane == 0) g_sw[p] = S * inv;
}

// ---------------- GEMM1: PF = R (16384x256) . w2bT (256x64) + sw*b2b ----------------
__global__ void __launch_bounds__(256) k_gemm_pf(const float* __restrict__ b2b) {
    __shared__ __align__(16) float Ast[16][132];
    __shared__ __align__(16) float Bs[16][64];
    int tid = threadIdx.x;
    int p0 = blockIdx.x * 128;
    int ty = tid >> 4, tx = tid & 15;
    int lp = tid >> 1, kh = (tid & 1) * 8;
    float acc[8][4];
    #pragma unroll
    for (int i = 0; i < 8; i++)
        #pragma unroll
        for (int j = 0; j < 4; j++) acc[i][j] = 0.f;
    for (int k0 = 0; k0 < HID_; k0 += 16) {
        const float* ap = g_R + (size_t)(p0+lp)*HID_ + k0 + kh;
        float4 a0 = *(const float4*)ap;
        float4 a1 = *(const float4*)(ap + 4);
        Ast[kh+0][lp]=a0.x; Ast[kh+1][lp]=a0.y; Ast[kh+2][lp]=a0.z; Ast[kh+3][lp]=a0.w;
        Ast[kh+4][lp]=a1.x; Ast[kh+5][lp]=a1.y; Ast[kh+6][lp]=a1.z; Ast[kh+7][lp]=a1.w;
        ((float4*)&Bs[0][0])[tid] = *(const float4*)(g_w2bT + k0*C_ + tid*4);
        __syncthreads();
        #pragma unroll
        for (int kk = 0; kk < 16; kk++) {
            float4 A0 = *(const float4*)&Ast[kk][ty*8];
            float4 A1 = *(const float4*)&Ast[kk][ty*8+4];
            float4 Bv = *(const float4*)&Bs[kk][tx*4];
            float a[8] = {A0.x,A0.y,A0.z,A0.w,A1.x,A1.y,A1.z,A1.w};
            float bb[4] = {Bv.x,Bv.y,Bv.z,Bv.w};
            #pragma unroll
            for (int i = 0; i < 8; i++)
                #pragma unroll
                for (int j = 0; j < 4; j++)
                    acc[i][j] = fmaf(a[i], bb[j], acc[i][j]);
        }
        __syncthreads();
    }
    #pragma unroll
    for (int i = 0; i < 8; i++) {
        int p = p0 + ty*8 + i;
        float swv = g_sw[p];
        float* dst = g_DF + (size_t)p*192 + 128 + tx*4;
        #pragma unroll
        for (int j = 0; j < 4; j++) dst[j] = acc[i][j] + swv * b2b[tx*4+j];
    }
}

// ---------------- GEMM2+3 fused: H1 = relu(DF . w1asT + b1as); OUT = H1 . w1bT + b1b --
__global__ void __launch_bounds__(256) k_gemm_out(const float* __restrict__ b1b,
                                                  float* __restrict__ out) {
    __shared__ __align__(16) float Ast[16][132];
    __shared__ __align__(16) float Bs[16][64];
    __shared__ __align__(16) float H1T[64][136];
    int tid = threadIdx.x;
    int p0 = blockIdx.x * 128;
    int ty = tid >> 4, tx = tid & 15;
    int lp = tid >> 1, kh = (tid & 1) * 8;
    float acc[8][4];
    #pragma unroll
    for (int i = 0; i < 8; i++)
        #pragma unroll
        for (int j = 0; j < 4; j++) acc[i][j] = 0.f;
    for (int k0 = 0; k0 < 192; k0 += 16) {
        const float* ap = g_DF + (size_t)(p0+lp)*192 + k0 + kh;
        float4 a0 = *(const float4*)ap;
        float4 a1 = *(const float4*)(ap + 4);
        Ast[kh+0][lp]=a0.x; Ast[kh+1][lp]=a0.y; Ast[kh+2][lp]=a0.z; Ast[kh+3][lp]=a0.w;
        Ast[kh+4][lp]=a1.x; Ast[kh+5][lp]=a1.y; Ast[kh+6][lp]=a1.z; Ast[kh+7][lp]=a1.w;
        ((float4*)&Bs[0][0])[tid] = *(const float4*)(g_w1asT + k0*C_ + tid*4);
        __syncthreads();
        #pragma unroll
        for (int kk = 0; kk < 16; kk++) {
            float4 A0 = *(const float4*)&Ast[kk][ty*8];
            float4 A1 = *(const float4*)&Ast[kk][ty*8+4];
            float4 Bv = *(const float4*)&Bs[kk][tx*4];
            float a[8] = {A0.x,A0.y,A0.z,A0.w,A1.x,A1.y,A1.z,A1.w};
            float bb[4] = {Bv.x,Bv.y,Bv.z,Bv.w};
            #pragma unroll
            for (int i = 0; i < 8; i++)
                #pragma unroll
                for (int j = 0; j < 4; j++)
                    acc[i][j] = fmaf(a[i], bb[j], acc[i][j]);
        }
        __syncthreads();
    }
    // relu + transpose-store H1 into shared
    #pragma unroll
    for (int j = 0; j < 4; j++) {
        int o = tx*4 + j;
        float bb = g_b1as[o];
        #pragma unroll
        for (int i = 0; i < 8; i++)
            H1T[o][ty*8+i] = fmaxf(acc[i][j] + bb, 0.f);
    }
    __syncthreads();
    float acc2[8][4];
    #pragma unroll
    for (int i = 0; i < 8; i++)
        #pragma unroll
        for (int j = 0; j < 4; j++) acc2[i][j] = 0.f;
    #pragma unroll 8
    for (int kc = 0; kc < 64; kc++) {
        float4 A0 = *(const float4*)&H1T[kc][ty*8];
        float4 A1 = *(const float4*)&H1T[kc][ty*8+4];
        float4 Bv = *(const float4*)(g_w1bT + kc*C_ + tx*4);
        float a[8] = {A0.x,A0.y,A0.z,A0.w,A1.x,A1.y,A1.z,A1.w};
        float bb[4] = {Bv.x,Bv.y,Bv.z,Bv.w};
        #pragma unroll
        for (int i = 0; i < 8; i++)
            #pragma unroll
            for (int j = 0; j < 4; j++)
                acc2[i][j] = fmaf(a[i], bb[j], acc2[i][j]);
    }
    #pragma unroll
    for (int i = 0; i < 8; i++) {
        float* dst = out + (size_t)(p0 + ty*8 + i)*C_ + tx*4;
        #pragma unroll
        for (int j = 0; j < 4; j++) dst[j] = acc2[i][j] + b1b[tx*4+j];
    }
}

// ---------------- launch ----------------
extern "C" void kernel_launch(void* const* d_in, const int* in_sizes, int n_in,
                              void* d_out, int out_size) {
    const float* pcl     = (const float*)d_in[0];
    const float* noise   = (const float*)d_in[1];
    const float* feature = (const float*)d_in[2];
    const float* w2a  = (const float*)d_in[3];
    const float* b2a  = (const float*)d_in[4];
    const float* g2a  = (const float*)d_in[5];
    const float* bt2a = (const float*)d_in[6];
    const float* w2b  = (const float*)d_in[7];
    const float* b2b  = (const float*)d_in[8];
    const float* w1a  = (const float*)d_in[9];
    const float* b1a  = (const float*)d_in[10];
    const float* g1a  = (const float*)d_in[11];
    const float* bt1a = (const float*)d_in[12];
    const float* w1b  = (const float*)d_in[13];
    const float* b1b  = (const float*)d_in[14];
    float* out = (float*)d_out;

    k_prep<<<1, 256>>>(w2a, b2a, g2a, bt2a, w2b, w1a, b1a, g1a, bt1a, w1b);
    k_vtab<<<(B_*M_*HID_)/256, 256>>>(pcl);
    k_close<<<512, 256>>>(pcl, noise);
    k_knn<<<1024, 256>>>(pcl);
    k_assemble<<<2048, 256>>>(pcl, noise, feature);
    k_gemm_pf<<<128, 256>>>(b2b);
    k_gemm_out<<<128, 256>>>(b1b, out);
}

// round 3
// speedup vs baseline: 2.0768x; 2.0768x over previous
#include <cuda_runtime.h>
#include <cfloat>

#define B_ 2
#define N_ 8192
#define M_ 4096
#define C_ 64
#define HID_ 256
#define KNN_ 15
#define P_ (B_*N_)

// ---------------- scratch (no allocations allowed) ----------------
__device__ float g_v[B_*M_*HID_];        // 8 MB : W2a'[:, :3] . pcl[m]
__device__ float g_R[(size_t)P_*HID_];   // 16 MB: weighted relu sums
__device__ float g_DF[(size_t)P_*192];   // 12 MB: [close_feat | co_feat | point_feat]
__device__ float g_sw[P_];               // sum of weights per point
__device__ int   g_close[P_];            // nearest clean index per noisy point
__device__ int   g_knn[B_*M_*KNN_];      // 15-NN (self excluded) per clean point
__device__ float g_w2as[HID_*6];         // BN-folded W2a
__device__ float g_b2as[HID_];
__device__ float g_w2bT[HID_*C_];        // W2b transposed [k][o]
__device__ float g_w1asT[192*C_];        // BN-folded W1a transposed [k][o]
__device__ float g_b1as[C_];
__device__ float g_w1bT[C_*C_];          // W1b transposed [k][o]

// ---------------- weight prep: fold BN scale, transpose ----------------
__global__ void k_prep(const float* __restrict__ w2a, const float* __restrict__ b2a,
                       const float* __restrict__ g2a, const float* __restrict__ bt2a,
                       const float* __restrict__ w2b, const float* __restrict__ w1a,
                       const float* __restrict__ b1a, const float* __restrict__ g1a,
                       const float* __restrict__ bt1a, const float* __restrict__ w1b) {
    int t = threadIdx.x;
    const float sc = rsqrtf(1.0f + 1e-5f);
    if (t < HID_) {
        float s = g2a[t] * sc;
        #pragma unroll
        for (int d = 0; d < 6; d++) g_w2as[t*6+d] = w2a[t*6+d] * s;
        g_b2as[t] = b2a[t] * s + bt2a[t];
    }
    if (t < C_) {
        float s = g1a[t] * sc;
        for (int j = 0; j < 192; j++) g_w1asT[j*C_+t] = w1a[t*192+j] * s;
        g_b1as[t] = b1a[t] * s + bt1a[t];
    }
    for (int i = t; i < HID_*C_; i += 256) { int j = i >> 6, o = i & 63; g_w2bT[i] = w2b[o*HID_+j]; }
    for (int i = t; i < C_*C_;  i += 256) { int j = i >> 6, o = i & 63; g_w1bT[i] = w1b[o*C_+j]; }
}

// ---------------- v table: v[b,m,c] = W2a'[c,0:3] . pcl[b,m] ----------------
__global__ void k_vtab(const float* __restrict__ pcl) {
    int idx = blockIdx.x * blockDim.x + threadIdx.x;   // B*M*HID threads
    if (idx >= B_*M_*HID_) return;
    int pm = idx >> 8, c = idx & 255;
    float x = pcl[pm*3], y = pcl[pm*3+1], z = pcl[pm*3+2];
    g_v[idx] = g_w2as[c*6]*x + g_w2as[c*6+1]*y + g_w2as[c*6+2]*z;
}

// ---------------- nearest clean point per noisy point ----------------
#define CT_ 2048
__global__ void __launch_bounds__(256) k_close(const float* __restrict__ pcl,
                                               const float* __restrict__ noise) {
    __shared__ float sx[CT_], sy[CT_], sz[CT_];
    __shared__ float rb[8][32];
    __shared__ int   ri[8][32];
    int blk = blockIdx.x;                 // 512 blocks: 256 per batch
    int b   = blk >> 8;
    int pt  = threadIdx.x & 31;
    int s   = threadIdx.x >> 5;           // 8-way split of M
    int n   = (blk & 255) * 32 + pt;
    const float* PB = pcl + b*M_*3;
    float nx = noise[(b*N_+n)*3+0], ny = noise[(b*N_+n)*3+1], nz = noise[(b*N_+n)*3+2];
    float best = FLT_MAX; int bi = 0;
    for (int t0 = 0; t0 < M_; t0 += CT_) {
        for (int i = threadIdx.x; i < CT_; i += 256) {
            sx[i] = PB[(t0+i)*3]; sy[i] = PB[(t0+i)*3+1]; sz[i] = PB[(t0+i)*3+2];
        }
        __syncthreads();
        int lo = s * (CT_/8), hi = lo + CT_/8;
        for (int i = lo; i < hi; i++) {
            float dx = sx[i]-nx, dy = sy[i]-ny, dz = sz[i]-nz;
            float d  = fmaf(dx, dx, fmaf(dy, dy, dz*dz));
            if (d < best) { best = d; bi = t0 + i; }
        }
        __syncthreads();
    }
    rb[s][pt] = best; ri[s][pt] = bi;
    __syncthreads();
    if (s == 0) {
        #pragma unroll
        for (int ss = 1; ss < 8; ss++) {
            float d = rb[ss][pt];
            if (d < best) { best = d; bi = ri[ss][pt]; }
        }
        g_close[b*N_+n] = bi;
    }
}

// ---------------- 15-NN per clean point: warp-cooperative distributed top-K ----
// Top-15 lives sorted (ascending) across lanes 0..14, one (dist,idx) per lane.
// Per 32-candidate batch: ballot finds candidates beating warp-uniform worst,
// each is inserted by one predicated shfl-shift of the whole list.
__global__ void __launch_bounds__(256) k_knn(const float* __restrict__ pcl) {
    __shared__ float sx[M_], sy[M_], sz[M_];      // 48 KB: whole batch cloud
    int blk  = blockIdx.x;                        // 1024 blocks: 512/batch, 8 pts each
    int b    = blk >> 9;
    int w    = threadIdx.x >> 5;
    int lane = threadIdx.x & 31;
    int m    = (blk & 511) * 8 + w;
    const float* PB = pcl + b*M_*3;
    for (int i = threadIdx.x; i < M_; i += 256) {
        sx[i] = PB[i*3]; sy[i] = PB[i*3+1]; sz[i] = PB[i*3+2];
    }
    __syncthreads();
    float qx = sx[m], qy = sy[m], qz = sz[m];
    float Dl = FLT_MAX;                           // list entry held by this lane
    int   Il = -1;
    float worst = FLT_MAX;                        // warp-uniform 15th best
    for (int t0 = 0; t0 < M_; t0 += 32) {
        int c = t0 + lane;
        float dx = sx[c]-qx, dy = sy[c]-qy, dz = sz[c]-qz;
        float d  = fmaf(dx, dx, fmaf(dy, dy, dz*dz));
        bool pass = (d < worst) & (c != m);
        unsigned mask = __ballot_sync(0xffffffffu, pass);
        while (mask) {                            // warp-uniform loop
            int s = __ffs(mask) - 1;
            mask &= mask - 1;
            float bd = __shfl_sync(0xffffffffu, d, s);
            int   bi = t0 + s;
            if (bd < worst) {                     // warp-uniform condition
                float pd = __shfl_up_sync(0xffffffffu, Dl, 1);
                int   pi = __shfl_up_sync(0xffffffffu, Il, 1);
                if (lane == 0) { pd = -FLT_MAX; pi = -1; }
                if (lane < KNN_ && Dl >= bd) {
                    if (pd >= bd) { Dl = pd; Il = pi; }
                    else          { Dl = bd; Il = bi; }
                }
                worst = __shfl_sync(0xffffffffu, Dl, KNN_ - 1);
            }
        }
    }
    if (lane < KNN_) g_knn[(b*M_+m)*KNN_ + lane] = Il;
}

// ---------------- assemble: weights, weighted relu sums R, df[0:128] ----------------
__global__ void __launch_bounds__(256) k_assemble(const float* __restrict__ pcl,
                                                  const float* __restrict__ noise,
                                                  const float* __restrict__ feature) {
    int w = threadIdx.x >> 5, lane = threadIdx.x & 31;
    int p = blockIdx.x * 8 + w;           // warp per noisy point
    int b = p >> 13;                      // N = 8192
    int m0 = g_close[p];
    const float* PB = pcl + b*M_*3;
    const float* FB = feature + b*M_*C_;
    float nx = noise[p*3], ny = noise[p*3+1], nz = noise[p*3+2];
    float cx = PB[m0*3], cy = PB[m0*3+1], cz = PB[m0*3+2];
    float t[8], r[8];
    #pragma unroll
    for (int j = 0; j < 8; j++) {
        int c = lane + 32*j;
        const float* wv = g_w2as + c*6;
        t[j] = g_b2as[c] + wv[3]*cx + wv[4]*cy + wv[5]*cz
                         - (wv[0]*nx + wv[1]*ny + wv[2]*nz);
        r[j] = 0.f;
    }
    float S = 0.f, co0 = 0.f, co1 = 0.f;
    const int* nbp = g_knn + (b*M_+m0)*KNN_;
    #pragma unroll 1
    for (int k = 0; k < KNN_; k++) {
        int nb = nbp[k];
        float dx = PB[nb*3]-nx, dy = PB[nb*3+1]-ny, dz = PB[nb*3+2]-nz;
        float dst = sqrtf(fmaf(dx, dx, fmaf(dy, dy, dz*dz)));
        float e = __expf(-10.f * dst);
        S += e;
        const float* vr = g_v + (nb + b*M_)*HID_;
        #pragma unroll
        for (int j = 0; j < 8; j++) {
            float h = vr[lane + 32*j] + t[j];
            r[j] = fmaf(e, fmaxf(h, 0.f), r[j]);
        }
        co0 = fmaf(e, FB[nb*C_+lane],    co0);
        co1 = fmaf(e, FB[nb*C_+32+lane], co1);
    }
    float inv = 1.f / (S + 1e-7f);
    float* Rr = g_R + (size_t)p*HID_;
    #pragma unroll
    for (int j = 0; j < 8; j++) Rr[lane + 32*j] = r[j] * inv;
    float* dfp = g_DF + (size_t)p*192;
    dfp[lane]       = FB[m0*C_+lane];
    dfp[32+lane]    = FB[m0*C_+32+lane];
    dfp[64+lane]    = co0 * inv;
    dfp[96+lane]    = co1 * inv;
    if (lane == 0) g_sw[p] = S * inv;
}

// ---------------- GEMM1: PF = R (16384x256) . w2bT (256x64) + sw*b2b ----------------
__global__ void __launch_bounds__(256) k_gemm_pf(const float* __restrict__ b2b) {
    __shared__ __align__(16) float Ast[16][132];
    __shared__ __align__(16) float Bs[16][64];
    int tid = threadIdx.x;
    int p0 = blockIdx.x * 128;
    int ty = tid >> 4, tx = tid & 15;
    int lp = tid >> 1, kh = (tid & 1) * 8;
    float acc[8][4];
    #pragma unroll
    for (int i = 0; i < 8; i++)
        #pragma unroll
        for (int j = 0; j < 4; j++) acc[i][j] = 0.f;
    for (int k0 = 0; k0 < HID_; k0 += 16) {
        const float* ap = g_R + (size_t)(p0+lp)*HID_ + k0 + kh;
        float4 a0 = *(const float4*)ap;
        float4 a1 = *(const float4*)(ap + 4);
        Ast[kh+0][lp]=a0.x; Ast[kh+1][lp]=a0.y; Ast[kh+2][lp]=a0.z; Ast[kh+3][lp]=a0.w;
        Ast[kh+4][lp]=a1.x; Ast[kh+5][lp]=a1.y; Ast[kh+6][lp]=a1.z; Ast[kh+7][lp]=a1.w;
        ((float4*)&Bs[0][0])[tid] = *(const float4*)(g_w2bT + k0*C_ + tid*4);
        __syncthreads();
        #pragma unroll
        for (int kk = 0; kk < 16; kk++) {
            float4 A0 = *(const float4*)&Ast[kk][ty*8];
            float4 A1 = *(const float4*)&Ast[kk][ty*8+4];
            float4 Bv = *(const float4*)&Bs[kk][tx*4];
            float a[8] = {A0.x,A0.y,A0.z,A0.w,A1.x,A1.y,A1.z,A1.w};
            float bb[4] = {Bv.x,Bv.y,Bv.z,Bv.w};
            #pragma unroll
            for (int i = 0; i < 8; i++)
                #pragma unroll
                for (int j = 0; j < 4; j++)
                    acc[i][j] = fmaf(a[i], bb[j], acc[i][j]);
        }
        __syncthreads();
    }
    #pragma unroll
    for (int i = 0; i < 8; i++) {
        int p = p0 + ty*8 + i;
        float swv = g_sw[p];
        float* dst = g_DF + (size_t)p*192 + 128 + tx*4;
        #pragma unroll
        for (int j = 0; j < 4; j++) dst[j] = acc[i][j] + swv * b2b[tx*4+j];
    }
}

// ---------------- GEMM2+3 fused: H1 = relu(DF . w1asT + b1as); OUT = H1 . w1bT + b1b --
__global__ void __launch_bounds__(256) k_gemm_out(const float* __restrict__ b1b,
                                                  float* __restrict__ out) {
    __shared__ __align__(16) float Ast[16][132];
    __shared__ __align__(16) float Bs[16][64];
    __shared__ __align__(16) float H1T[64][136];
    int tid = threadIdx.x;
    int p0 = blockIdx.x * 128;
    int ty = tid >> 4, tx = tid & 15;
    int lp = tid >> 1, kh = (tid & 1) * 8;
    float acc[8][4];
    #pragma unroll
    for (int i = 0; i < 8; i++)
        #pragma unroll
        for (int j = 0; j < 4; j++) acc[i][j] = 0.f;
    for (int k0 = 0; k0 < 192; k0 += 16) {
        const float* ap = g_DF + (size_t)(p0+lp)*192 + k0 + kh;
        float4 a0 = *(const float4*)ap;
        float4 a1 = *(const float4*)(ap + 4);
        Ast[kh+0][lp]=a0.x; Ast[kh+1][lp]=a0.y; Ast[kh+2][lp]=a0.z; Ast[kh+3][lp]=a0.w;
        Ast[kh+4][lp]=a1.x; Ast[kh+5][lp]=a1.y; Ast[kh+6][lp]=a1.z; Ast[kh+7][lp]=a1.w;
        ((float4*)&Bs[0][0])[tid] = *(const float4*)(g_w1asT + k0*C_ + tid*4);
        __syncthreads();
        #pragma unroll
        for (int kk = 0; kk < 16; kk++) {
            float4 A0 = *(const float4*)&Ast[kk][ty*8];
            float4 A1 = *(const float4*)&Ast[kk][ty*8+4];
            float4 Bv = *(const float4*)&Bs[kk][tx*4];
            float a[8] = {A0.x,A0.y,A0.z,A0.w,A1.x,A1.y,A1.z,A1.w};
            float bb[4] = {Bv.x,Bv.y,Bv.z,Bv.w};
            #pragma unroll
            for (int i = 0; i < 8; i++)
                #pragma unroll
                for (int j = 0; j < 4; j++)
                    acc[i][j] = fmaf(a[i], bb[j], acc[i][j]);
        }
        __syncthreads();
    }
    // relu + transpose-store H1 into shared
    #pragma unroll
    for (int j = 0; j < 4; j++) {
        int o = tx*4 + j;
        float bb = g_b1as[o];
        #pragma unroll
        for (int i = 0; i < 8; i++)
            H1T[o][ty*8+i] = fmaxf(acc[i][j] + bb, 0.f);
    }
    __syncthreads();
    float acc2[8][4];
    #pragma unroll
    for (int i = 0; i < 8; i++)
        #pragma unroll
        for (int j = 0; j < 4; j++) acc2[i][j] = 0.f;
    #pragma unroll 8
    for (int kc = 0; kc < 64; kc++) {
        float4 A0 = *(const float4*)&H1T[kc][ty*8];
        float4 A1 = *(const float4*)&H1T[kc][ty*8+4];
        float4 Bv = *(const float4*)(g_w1bT + kc*C_ + tx*4);
        float a[8] = {A0.x,A0.y,A0.z,A0.w,A1.x,A1.y,A1.z,A1.w};
        float bb[4] = {Bv.x,Bv.y,Bv.z,Bv.w};
        #pragma unroll
        for (int i = 0; i < 8; i++)
            #pragma unroll
            for (int j = 0; j < 4; j++)
                acc2[i][j] = fmaf(a[i], bb[j], acc2[i][j]);
    }
    #pragma unroll
    for (int i = 0; i < 8; i++) {
        float* dst = out + (size_t)(p0 + ty*8 + i)*C_ + tx*4;
        #pragma unroll
        for (int j = 0; j < 4; j++) dst[j] = acc2[i][j] + b1b[tx*4+j];
    }
}

// ---------------- launch ----------------
extern "C" void kernel_launch(void* const* d_in, const int* in_sizes, int n_in,
                              void* d_out, int out_size) {
    const float* pcl     = (const float*)d_in[0];
    const float* noise   = (const float*)d_in[1];
    const float* feature = (const float*)d_in[2];
    const float* w2a  = (const float*)d_in[3];
    const float* b2a  = (const float*)d_in[4];
    const float* g2a  = (const float*)d_in[5];
    const float* bt2a = (const float*)d_in[6];
    const float* w2b  = (const float*)d_in[7];
    const float* b2b  = (const float*)d_in[8];
    const float* w1a  = (const float*)d_in[9];
    const float* b1a  = (const float*)d_in[10];
    const float* g1a  = (const float*)d_in[11];
    const float* bt1a = (const float*)d_in[12];
    const float* w1b  = (const float*)d_in[13];
    const float* b1b  = (const float*)d_in[14];
    float* out = (float*)d_out;

    k_prep<<<1, 256>>>(w2a, b2a, g2a, bt2a, w2b, w1a, b1a, g1a, bt1a, w1b);
    k_vtab<<<(B_*M_*HID_)/256, 256>>>(pcl);
    k_close<<<512, 256>>>(pcl, noise);
    k_knn<<<1024, 256>>>(pcl);
    k_assemble<<<2048, 256>>>(pcl, noise, feature);
    k_gemm_pf<<<128, 256>>>(b2b);
    k_gemm_out<<<128, 256>>>(b1b, out);
}

// round 4
// speedup vs baseline: 2.2184x; 1.0682x over previous
#include <cuda_runtime.h>
#include <cfloat>

#define B_ 2
#define N_ 8192
#define M_ 4096
#define C_ 64
#define HID_ 256
#define KNN_ 15
#define P_ (B_*N_)

// ---------------- scratch (no allocations allowed) ----------------
__device__ float  g_v[B_*M_*HID_];        // 8 MB : W2a'[:, :3] . pcl[m]
__device__ float4 g_pc4[B_*M_];           // (x,y,z,|c|^2) per clean point
__device__ float  g_R[(size_t)P_*HID_];   // 16 MB: weighted relu sums
__device__ float  g_DF[(size_t)P_*128];   // 8 MB : [close_feat | co_feat]
__device__ float  g_sw[P_];               // sum of weights per point
__device__ unsigned long long g_ckey[P_]; // packed (dist,idx) argmin key
__device__ int    g_knn[B_*M_*KNN_];      // 15-NN (self excluded) per clean point
__device__ float  g_w2as[HID_*6];         // BN-folded W2a
__device__ float  g_b2as[HID_];
__device__ float  g_w1cat[384*C_];        // [ W1a'[:, :128] ; W' = w2bT . W1a'[:,128:192] ]
__device__ float  g_bb2[C_];              // b2b . W1a'[:,128:192]
__device__ float  g_b1as[C_];
__device__ float  g_w1bT[C_*C_];          // W1b transposed [k][o]

// ---------------- weight prep: fold BN scale, transpose ----------------
__global__ void k_prep(const float* __restrict__ w2a, const float* __restrict__ b2a,
                       const float* __restrict__ g2a, const float* __restrict__ bt2a,
                       const float* __restrict__ b1a, const float* __restrict__ g1a,
                       const float* __restrict__ bt1a, const float* __restrict__ w1b) {
    int t = threadIdx.x;
    const float sc = rsqrtf(1.0f + 1e-5f);
    if (t < HID_) {
        float s = g2a[t] * sc;
        #pragma unroll
        for (int d = 0; d < 6; d++) g_w2as[t*6+d] = w2a[t*6+d] * s;
        g_b2as[t] = b2a[t] * s + bt2a[t];
    }
    if (t < C_) {
        float s = g1a[t] * sc;
        g_b1as[t] = b1a[t] * s + bt1a[t];
    }
    for (int i = t; i < C_*C_;  i += 256) { int j = i >> 6, o = i & 63; g_w1bT[i] = w1b[o*C_+j]; }
}

// W' fold: g_w1cat[k][o]: k<128 -> W1a'[o][k]; k>=128 -> sum_h w2bT[k-128][h]*W1a'[o][128+h]
__global__ void k_prepw(const float* __restrict__ w2b, const float* __restrict__ w1a,
                        const float* __restrict__ g1a, const float* __restrict__ b2b) {
    int idx = blockIdx.x * 256 + threadIdx.x;      // 384*64 = 24576 -> grid 96
    if (idx >= 384*C_) return;
    int k = idx >> 6, o = idx & 63;
    float s = g1a[o] * rsqrtf(1.0f + 1e-5f);
    float val;
    if (k < 128) val = w1a[o*192 + k] * s;
    else {
        int h = k - 128;
        float acc = 0.f;
        #pragma unroll 8
        for (int o2 = 0; o2 < C_; o2++) acc += w2b[o2*HID_ + h] * w1a[o*192 + 128 + o2];
        val = acc * s;
    }
    g_w1cat[k*C_ + o] = val;
    if (idx < C_) {            // k==0 lane set: bias fold for output o=idx
        float acc = 0.f;
        for (int o2 = 0; o2 < C_; o2++) acc += b2b[o2] * w1a[idx*192 + 128 + o2];
        g_bb2[idx] = acc * s;
    }
}

// ---------------- v table + pc4 + ckey init ----------------
__global__ void k_vtab(const float* __restrict__ pcl) {
    int idx = blockIdx.x * blockDim.x + threadIdx.x;   // B*M*HID threads
    if (idx >= B_*M_*HID_) return;
    if (idx < B_*M_) {
        float x = pcl[idx*3], y = pcl[idx*3+1], z = pcl[idx*3+2];
        g_pc4[idx] = make_float4(x, y, z, fmaf(x,x, fmaf(y,y, z*z)));
    }
    if (idx < P_) g_ckey[idx] = 0xFFFFFFFFFFFFFFFFull;
    int pm = idx >> 8, c = idx & 255;
    float x = pcl[pm*3], y = pcl[pm*3+1], z = pcl[pm*3+2];
    g_v[idx] = g_w2as[c*6]*x + g_w2as[c*6+1]*y + g_w2as[c*6+2]*z;
}

// ---------------- nearest clean point: 8 queries/thread, atomic argmin merge ----
#define CLQ_ 8
__global__ void __launch_bounds__(256) k_close(const float* __restrict__ noise) {
    int qg = blockIdx.x >> 5;                  // 8 query groups of 2048
    int ms = blockIdx.x & 31;                  // 32 M-chunks of 128
    int p0 = qg * 2048 + threadIdx.x * CLQ_;
    int b  = p0 >> 13;
    const float4* PC = g_pc4 + b*M_;
    float qx[CLQ_], qy[CLQ_], qz[CLQ_], bd[CLQ_];
    int bi[CLQ_];
    #pragma unroll
    for (int q = 0; q < CLQ_; q++) {
        const float* np = noise + (size_t)(p0+q)*3;
        qx[q] = -2.f*np[0]; qy[q] = -2.f*np[1]; qz[q] = -2.f*np[2];
        bd[q] = FLT_MAX; bi[q] = 0;
    }
    int c0 = ms * 128;
    #pragma unroll 2
    for (int i = 0; i < 128; i++) {
        float4 c = __ldg(&PC[c0 + i]);
        #pragma unroll
        for (int q = 0; q < CLQ_; q++) {
            float d = fmaf(c.x, qx[q], fmaf(c.y, qy[q], fmaf(c.z, qz[q], c.w)));
            if (d < bd[q]) { bd[q] = d; bi[q] = c0 + i; }
        }
    }
    #pragma unroll
    for (int q = 0; q < CLQ_; q++) {
        unsigned u = __float_as_uint(bd[q]);
        u = (u & 0x80000000u) ? ~u : (u | 0x80000000u);   // order-preserving map
        unsigned long long key = ((unsigned long long)u << 32) | (unsigned)bi[q];
        atomicMin(&g_ckey[p0+q], key);
    }
}

// ---------------- 15-NN per clean point: warp-cooperative distributed top-K ----
__global__ void __launch_bounds__(512) k_knn() {
    extern __shared__ float4 sc[];                // 64 KB: whole batch cloud
    int blk  = blockIdx.x;                        // 512 blocks: 256/batch, 16 pts each
    int b    = blk >> 8;
    int w    = threadIdx.x >> 5;
    int lane = threadIdx.x & 31;
    int m    = (blk & 255) * 16 + w;
    const float4* PC = g_pc4 + b*M_;
    for (int i = threadIdx.x; i < M_; i += 512) sc[i] = PC[i];
    __syncthreads();
    float4 qc = sc[m];
    float qx = -2.f*qc.x, qy = -2.f*qc.y, qz = -2.f*qc.z;
    float Dl = FLT_MAX;                           // list entry held by this lane
    int   Il = -1;
    float worst = FLT_MAX;                        // warp-uniform 15th best
    for (int t0 = 0; t0 < M_; t0 += 32) {
        int c = t0 + lane;
        float4 cc = sc[c];
        float d = fmaf(cc.x, qx, fmaf(cc.y, qy, fmaf(cc.z, qz, cc.w)));
        bool pass = (d < worst) & (c != m);
        unsigned mask = __ballot_sync(0xffffffffu, pass);
        while (mask) {                            // warp-uniform loop
            int s = __ffs(mask) - 1;
            mask &= mask - 1;
            float bd = __shfl_sync(0xffffffffu, d, s);
            int   bix = t0 + s;
            if (bd < worst) {                     // warp-uniform condition
                float pd = __shfl_up_sync(0xffffffffu, Dl, 1);
                int   pi = __shfl_up_sync(0xffffffffu, Il, 1);
                if (lane == 0) { pd = -FLT_MAX; pi = -1; }
                if (lane < KNN_ && Dl >= bd) {
                    if (pd >= bd) { Dl = pd; Il = pi; }
                    else          { Dl = bd; Il = bix; }
                }
                worst = __shfl_sync(0xffffffffu, Dl, KNN_ - 1);
            }
        }
    }
    if (lane < KNN_) g_knn[(b*M_+m)*KNN_ + lane] = Il;
}

// ---------------- assemble: weights, weighted relu sums R, df[0:128] ----------------
__global__ void __launch_bounds__(256) k_assemble(const float* __restrict__ pcl,
                                                  const float* __restrict__ noise,
                                                  const float* __restrict__ feature) {
    int w = threadIdx.x >> 5, lane = threadIdx.x & 31;
    int p = blockIdx.x * 8 + w;           // warp per noisy point
    int b = p >> 13;                      // N = 8192
    int m0 = (int)(g_ckey[p] & 0xFFFFFFFFull);
    const float* PB = pcl + b*M_*3;
    const float* FB = feature + b*M_*C_;
    float nx = noise[p*3], ny = noise[p*3+1], nz = noise[p*3+2];
    float cx = PB[m0*3], cy = PB[m0*3+1], cz = PB[m0*3+2];
    float t[8], r[8];
    #pragma unroll
    for (int j = 0; j < 8; j++) {
        int c = lane + 32*j;
        const float* wv = g_w2as + c*6;
        t[j] = g_b2as[c] + wv[3]*cx + wv[4]*cy + wv[5]*cz
                         - (wv[0]*nx + wv[1]*ny + wv[2]*nz);
        r[j] = 0.f;
    }
    float S = 0.f, co0 = 0.f, co1 = 0.f;
    const int* nbp = g_knn + (b*M_+m0)*KNN_;
    #pragma unroll 1
    for (int k = 0; k < KNN_; k++) {
        int nb = nbp[k];
        float dx = PB[nb*3]-nx, dy = PB[nb*3+1]-ny, dz = PB[nb*3+2]-nz;
        float dst = sqrtf(fmaf(dx, dx, fmaf(dy, dy, dz*dz)));
        float e = __expf(-10.f * dst);
        S += e;
        const float* vr = g_v + (nb + b*M_)*HID_;
        #pragma unroll
        for (int j = 0; j < 8; j++) {
            float h = vr[lane + 32*j] + t[j];
            r[j] = fmaf(e, fmaxf(h, 0.f), r[j]);
        }
        co0 = fmaf(e, FB[nb*C_+lane],    co0);
        co1 = fmaf(e, FB[nb*C_+32+lane], co1);
    }
    float inv = 1.f / (S + 1e-7f);
    float* Rr = g_R + (size_t)p*HID_;
    #pragma unroll
    for (int j = 0; j < 8; j++) Rr[lane + 32*j] = r[j] * inv;
    float* dfp = g_DF + (size_t)p*128;
    dfp[lane]       = FB[m0*C_+lane];
    dfp[32+lane]    = FB[m0*C_+32+lane];
    dfp[64+lane]    = co0 * inv;
    dfp[96+lane]    = co1 * inv;
    if (lane == 0) g_sw[p] = S * inv;
}

// ---------------- fused GEMM: H1 = relu([DF|R].w1cat + b1as + sw*bb2); out = H1.w1bT + b1b
__global__ void __launch_bounds__(256) k_gemm(const float* __restrict__ b1b,
                                              float* __restrict__ out) {
    __shared__ __align__(16) float Ast[16][132];
    __shared__ __align__(16) float Bs[16][64];
    __shared__ __align__(16) float H1T[64][136];
    int tid = threadIdx.x;
    int p0 = blockIdx.x * 128;
    int ty = tid >> 4, tx = tid & 15;
    int lp = tid >> 1, kh = (tid & 1) * 8;
    float acc[8][4];
    #pragma unroll
    for (int i = 0; i < 8; i++)
        #pragma unroll
        for (int j = 0; j < 4; j++) acc[i][j] = 0.f;
    for (int k0 = 0; k0 < 384; k0 += 16) {
        const float* ap = (k0 < 128)
            ? g_DF + (size_t)(p0+lp)*128 + k0 + kh
            : g_R  + (size_t)(p0+lp)*HID_ + (k0 - 128) + kh;
        float4 a0 = *(const float4*)ap;
        float4 a1 = *(const float4*)(ap + 4);
        Ast[kh+0][lp]=a0.x; Ast[kh+1][lp]=a0.y; Ast[kh+2][lp]=a0.z; Ast[kh+3][lp]=a0.w;
        Ast[kh+4][lp]=a1.x; Ast[kh+5][lp]=a1.y; Ast[kh+6][lp]=a1.z; Ast[kh+7][lp]=a1.w;
        ((float4*)&Bs[0][0])[tid] = *(const float4*)(g_w1cat + k0*C_ + tid*4);
        __syncthreads();
        #pragma unroll
        for (int kk = 0; kk < 16; kk++) {
            float4 A0 = *(const float4*)&Ast[kk][ty*8];
            float4 A1 = *(const float4*)&Ast[kk][ty*8+4];
            float4 Bv = *(const float4*)&Bs[kk][tx*4];
            float a[8] = {A0.x,A0.y,A0.z,A0.w,A1.x,A1.y,A1.z,A1.w};
            float bb[4] = {Bv.x,Bv.y,Bv.z,Bv.w};
            #pragma unroll
            for (int i = 0; i < 8; i++)
                #pragma unroll
                for (int j = 0; j < 4; j++)
                    acc[i][j] = fmaf(a[i], bb[j], acc[i][j]);
        }
        __syncthreads();
    }
    // epilogue stage 1: relu + transpose-store H1 into shared
    float swv[8];
    #pragma unroll
    for (int i = 0; i < 8; i++) swv[i] = g_sw[p0 + ty*8 + i];
    #pragma unroll
    for (int j = 0; j < 4; j++) {
        int o = tx*4 + j;
        float bb = g_b1as[o], b2 = g_bb2[o];
        #pragma unroll
        for (int i = 0; i < 8; i++)
            H1T[o][ty*8+i] = fmaxf(acc[i][j] + bb + swv[i]*b2, 0.f);
    }
    __syncthreads();
    float acc2[8][4];
    #pragma unroll
    for (int i = 0; i < 8; i++)
        #pragma unroll
        for (int j = 0; j < 4; j++) acc2[i][j] = 0.f;
    #pragma unroll 8
    for (int kc = 0; kc < 64; kc++) {
        float4 A0 = *(const float4*)&H1T[kc][ty*8];
        float4 A1 = *(const float4*)&H1T[kc][ty*8+4];
        float4 Bv = *(const float4*)(g_w1bT + kc*C_ + tx*4);
        float a[8] = {A0.x,A0.y,A0.z,A0.w,A1.x,A1.y,A1.z,A1.w};
        float bb[4] = {Bv.x,Bv.y,Bv.z,Bv.w};
        #pragma unroll
        for (int i = 0; i < 8; i++)
            #pragma unroll
            for (int j = 0; j < 4; j++)
                acc2[i][j] = fmaf(a[i], bb[j], acc2[i][j]);
    }
    #pragma unroll
    for (int i = 0; i < 8; i++) {
        float* dst = out + (size_t)(p0 + ty*8 + i)*C_ + tx*4;
        #pragma unroll
        for (int j = 0; j < 4; j++) dst[j] = acc2[i][j] + b1b[tx*4+j];
    }
}

// ---------------- launch ----------------
extern "C" void kernel_launch(void* const* d_in, const int* in_sizes, int n_in,
                              void* d_out, int out_size) {
    const float* pcl     = (const float*)d_in[0];
    const float* noise   = (const float*)d_in[1];
    const float* feature = (const float*)d_in[2];
    const float* w2a  = (const float*)d_in[3];
    const float* b2a  = (const float*)d_in[4];
    const float* g2a  = (const float*)d_in[5];
    const float* bt2a = (const float*)d_in[6];
    const float* w2b  = (const float*)d_in[7];
    const float* b2b  = (const float*)d_in[8];
    const float* w1a  = (const float*)d_in[9];
    const float* b1a  = (const float*)d_in[10];
    const float* g1a  = (const float*)d_in[11];
    const float* bt1a = (const float*)d_in[12];
    const float* w1b  = (const float*)d_in[13];
    const float* b1b  = (const float*)d_in[14];
    float* out = (float*)d_out;

    cudaFuncSetAttribute(k_knn, cudaFuncAttributeMaxDynamicSharedMemorySize, M_*16);

    k_prep<<<1, 256>>>(w2a, b2a, g2a, bt2a, b1a, g1a, bt1a, w1b);
    k_prepw<<<96, 256>>>(w2b, w1a, g1a, b2b);
    k_vtab<<<(B_*M_*HID_)/256, 256>>>(pcl);
    k_close<<<256, 256>>>(noise);
    k_knn<<<512, 512, M_*16>>>();
    k_assemble<<<2048, 256>>>(pcl, noise, feature);
    k_gemm<<<128, 256>>>(b1b, out);
}

// round 6
// speedup vs baseline: 2.2741x; 1.0251x over previous
#include <cuda_runtime.h>
#include <cfloat>

#define B_ 2
#define N_ 8192
#define M_ 4096
#define C_ 64
#define HID_ 256
#define KNN_ 15
#define P_ (B_*N_)

// ---------------- scratch (no allocations allowed) ----------------
__device__ float  g_v[B_*M_*HID_];        // 8 MB : W2a'[:, :3] . pcl[m]
__device__ float4 g_pc4[B_*M_];           // (x,y,z,|c|^2) per clean point
__device__ float  g_R[(size_t)P_*HID_];   // 16 MB: weighted relu sums
__device__ float  g_DF[(size_t)P_*128];   // 8 MB : [close_feat | co_feat]
__device__ float  g_sw[P_];               // sum of weights per point
__device__ unsigned long long g_ckey[P_]; // packed (dist,idx) argmin key
__device__ int    g_knn[B_*M_*KNN_];      // 15-NN (self excluded) per clean point
__device__ float  g_w2as[HID_*6];         // BN-folded W2a
__device__ float  g_b2as[HID_];
__device__ float  g_w1cat[384*C_];        // [ W1a'[:, :128] ; W' = w2bT . W1a'[:,128:192] ]
__device__ float  g_bb2[C_];              // b2b . W1a'[:,128:192]
__device__ float  g_b1as[C_];
__device__ float  g_w1bT[C_*C_];          // W1b transposed [k][o]

// ---------------- weight prep: fold BN scale, transpose ----------------
__global__ void k_prep(const float* __restrict__ w2a, const float* __restrict__ b2a,
                       const float* __restrict__ g2a, const float* __restrict__ bt2a,
                       const float* __restrict__ b1a, const float* __restrict__ g1a,
                       const float* __restrict__ bt1a, const float* __restrict__ w1b) {
    int t = threadIdx.x;
    const float sc = rsqrtf(1.0f + 1e-5f);
    if (t < HID_) {
        float s = g2a[t] * sc;
        #pragma unroll
        for (int d = 0; d < 6; d++) g_w2as[t*6+d] = w2a[t*6+d] * s;
        g_b2as[t] = b2a[t] * s + bt2a[t];
    }
    if (t < C_) {
        float s = g1a[t] * sc;
        g_b1as[t] = b1a[t] * s + bt1a[t];
    }
    for (int i = t; i < C_*C_;  i += 256) { int j = i >> 6, o = i & 63; g_w1bT[i] = w1b[o*C_+j]; }
}

// W' fold: g_w1cat[k][o]: k<128 -> W1a'[o][k]; k>=128 -> sum_h w2bT[k-128][h]*W1a'[o][128+h]
__global__ void k_prepw(const float* __restrict__ w2b, const float* __restrict__ w1a,
                        const float* __restrict__ g1a, const float* __restrict__ b2b) {
    int idx = blockIdx.x * 256 + threadIdx.x;      // 384*64 = 24576 -> grid 96
    if (idx >= 384*C_) return;
    int k = idx >> 6, o = idx & 63;
    float s = g1a[o] * rsqrtf(1.0f + 1e-5f);
    float val;
    if (k < 128) val = w1a[o*192 + k] * s;
    else {
        int h = k - 128;
        float acc = 0.f;
        #pragma unroll 8
        for (int o2 = 0; o2 < C_; o2++) acc += w2b[o2*HID_ + h] * w1a[o*192 + 128 + o2];
        val = acc * s;
    }
    g_w1cat[k*C_ + o] = val;
    if (idx < C_) {            // k==0 lane set: bias fold for output o=idx
        float acc = 0.f;
        for (int o2 = 0; o2 < C_; o2++) acc += b2b[o2] * w1a[idx*192 + 128 + o2];
        g_bb2[idx] = acc * s;
    }
}

// ---------------- v table + pc4 + ckey init ----------------
__global__ void k_vtab(const float* __restrict__ pcl) {
    int idx = blockIdx.x * blockDim.x + threadIdx.x;   // B*M*HID threads
    if (idx >= B_*M_*HID_) return;
    if (idx < B_*M_) {
        float x = pcl[idx*3], y = pcl[idx*3+1], z = pcl[idx*3+2];
        g_pc4[idx] = make_float4(x, y, z, fmaf(x,x, fmaf(y,y, z*z)));
    }
    if (idx < P_) g_ckey[idx] = 0xFFFFFFFFFFFFFFFFull;
    int pm = idx >> 8, c = idx & 255;
    float x = pcl[pm*3], y = pcl[pm*3+1], z = pcl[pm*3+2];
    g_v[idx] = g_w2as[c*6]*x + g_w2as[c*6+1]*y + g_w2as[c*6+2]*z;
}

// ---------------- nearest clean point: 4 queries/thread, one balanced wave ----
// grid = 16 query-groups (1024 queries each) x 32 M-chunks (128 cands) = 512 blocks
#define CLQ_ 4
__global__ void __launch_bounds__(256) k_close(const float* __restrict__ noise) {
    int qg = blockIdx.x >> 5;                  // 16 query groups of 1024
    int ms = blockIdx.x & 31;                  // 32 M-chunks of 128
    int p0 = qg * 1024 + threadIdx.x * CLQ_;
    int b  = p0 >> 13;
    const float4* PC = g_pc4 + b*M_;
    float qx[CLQ_], qy[CLQ_], qz[CLQ_], bd[CLQ_];
    int bi[CLQ_];
    #pragma unroll
    for (int q = 0; q < CLQ_; q++) {
        const float* np = noise + (size_t)(p0+q)*3;
        qx[q] = -2.f*np[0]; qy[q] = -2.f*np[1]; qz[q] = -2.f*np[2];
        bd[q] = FLT_MAX; bi[q] = 0;
    }
    int c0 = ms * 128;
    #pragma unroll 4
    for (int i = 0; i < 128; i++) {
        float4 c = __ldg(&PC[c0 + i]);
        #pragma unroll
        for (int q = 0; q < CLQ_; q++) {
            float d = fmaf(c.x, qx[q], fmaf(c.y, qy[q], fmaf(c.z, qz[q], c.w)));
            if (d < bd[q]) { bd[q] = d; bi[q] = c0 + i; }
        }
    }
    #pragma unroll
    for (int q = 0; q < CLQ_; q++) {
        unsigned u = __float_as_uint(bd[q]);
        u = (u & 0x80000000u) ? ~u : (u | 0x80000000u);   // order-preserving map
        unsigned long long key = ((unsigned long long)u << 32) | (unsigned)bi[q];
        atomicMin(&g_ckey[p0+q], key);
    }
}

// ---------------- 15-NN per clean point: warp-cooperative distributed top-K ----
__global__ void __launch_bounds__(512) k_knn() {
    extern __shared__ float4 sc[];                // 64 KB: whole batch cloud
    int blk  = blockIdx.x;                        // 512 blocks: 256/batch, 16 pts each
    int b    = blk >> 8;
    int w    = threadIdx.x >> 5;
    int lane = threadIdx.x & 31;
    int m    = (blk & 255) * 16 + w;
    const float4* PC = g_pc4 + b*M_;
    for (int i = threadIdx.x; i < M_; i += 512) sc[i] = PC[i];
    __syncthreads();
    float4 qc = sc[m];
    float qx = -2.f*qc.x, qy = -2.f*qc.y, qz = -2.f*qc.z;
    float Dl = FLT_MAX;                           // list entry held by this lane
    int   Il = -1;
    float worst = FLT_MAX;                        // warp-uniform 15th best
    for (int t0 = 0; t0 < M_; t0 += 32) {
        int c = t0 + lane;
        float4 cc = sc[c];
        float d = fmaf(cc.x, qx, fmaf(cc.y, qy, fmaf(cc.z, qz, cc.w)));
        bool pass = (d < worst) & (c != m);
        unsigned mask = __ballot_sync(0xffffffffu, pass);
        while (mask) {                            // warp-uniform loop
            int s = __ffs(mask) - 1;
            mask &= mask - 1;
            float bd = __shfl_sync(0xffffffffu, d, s);
            int   bix = t0 + s;
            if (bd < worst) {                     // warp-uniform condition
                float pd = __shfl_up_sync(0xffffffffu, Dl, 1);
                int   pi = __shfl_up_sync(0xffffffffu, Il, 1);
                if (lane == 0) { pd = -FLT_MAX; pi = -1; }
                if (lane < KNN_ && Dl >= bd) {
                    if (pd >= bd) { Dl = pd; Il = pi; }
                    else          { Dl = bd; Il = bix; }
                }
                worst = __shfl_sync(0xffffffffu, Dl, KNN_ - 1);
            }
        }
    }
    if (lane < KNN_) g_knn[(b*M_+m)*KNN_ + lane] = Il;
}

// ---------------- assemble: weights, weighted relu sums R, df[0:128] ----------------
__global__ void __launch_bounds__(256) k_assemble(const float* __restrict__ pcl,
                                                  const float* __restrict__ noise,
                                                  const float* __restrict__ feature) {
    int w = threadIdx.x >> 5, lane = threadIdx.x & 31;
    int p = blockIdx.x * 8 + w;           // warp per noisy point
    int b = p >> 13;                      // N = 8192
    int m0 = (int)(g_ckey[p] & 0xFFFFFFFFull);
    const float* PB = pcl + b*M_*3;
    const float* FB = feature + b*M_*C_;
    float nx = noise[p*3], ny = noise[p*3+1], nz = noise[p*3+2];
    float cx = PB[m0*3], cy = PB[m0*3+1], cz = PB[m0*3+2];
    float t[8], r[8];
    #pragma unroll
    for (int j = 0; j < 8; j++) {
        int c = lane + 32*j;
        const float* wv = g_w2as + c*6;
        t[j] = g_b2as[c] + wv[3]*cx + wv[4]*cy + wv[5]*cz
                         - (wv[0]*nx + wv[1]*ny + wv[2]*nz);
        r[j] = 0.f;
    }
    float S = 0.f, co0 = 0.f, co1 = 0.f;
    const int* nbp = g_knn + (b*M_+m0)*KNN_;
    #pragma unroll 1
    for (int k = 0; k < KNN_; k++) {
        int nb = nbp[k];
        float dx = PB[nb*3]-nx, dy = PB[nb*3+1]-ny, dz = PB[nb*3+2]-nz;
        float dst = sqrtf(fmaf(dx, dx, fmaf(dy, dy, dz*dz)));
        float e = __expf(-10.f * dst);
        S += e;
        const float* vr = g_v + (nb + b*M_)*HID_;
        #pragma unroll
        for (int j = 0; j < 8; j++) {
            float h = vr[lane + 32*j] + t[j];
            r[j] = fmaf(e, fmaxf(h, 0.f), r[j]);
        }
        co0 = fmaf(e, FB[nb*C_+lane],    co0);
        co1 = fmaf(e, FB[nb*C_+32+lane], co1);
    }
    float inv = 1.f / (S + 1e-7f);
    float* Rr = g_R + (size_t)p*HID_;
    #pragma unroll
    for (int j = 0; j < 8; j++) Rr[lane + 32*j] = r[j] * inv;
    float* dfp = g_DF + (size_t)p*128;
    dfp[lane]       = FB[m0*C_+lane];
    dfp[32+lane]    = FB[m0*C_+32+lane];
    dfp[64+lane]    = co0 * inv;
    dfp[96+lane]    = co1 * inv;
    if (lane == 0) g_sw[p] = S * inv;
}

// ---------------- fused GEMM: H1 = relu([DF|R].w1cat + b1as + sw*bb2); out = H1.w1bT + b1b
__global__ void __launch_bounds__(256) k_gemm(const float* __restrict__ b1b,
                                              float* __restrict__ out) {
    __shared__ __align__(16) float Ast[16][132];
    __shared__ __align__(16) float Bs[16][64];
    __shared__ __align__(16) float H1T[64][136];
    int tid = threadIdx.x;
    int p0 = blockIdx.x * 128;
    int ty = tid >> 4, tx = tid & 15;
    int lp = tid >> 1, kh = (tid & 1) * 8;
    float acc[8][4];
    #pragma unroll
    for (int i = 0; i < 8; i++)
        #pragma unroll
        for (int j = 0; j < 4; j++) acc[i][j] = 0.f;
    for (int k0 = 0; k0 < 384; k0 += 16) {
        const float* ap = (k0 < 128)
            ? g_DF + (size_t)(p0+lp)*128 + k0 + kh
            : g_R  + (size_t)(p0+lp)*HID_ + (k0 - 128) + kh;
        float4 a0 = *(const float4*)ap;
        float4 a1 = *(const float4*)(ap + 4);
        Ast[kh+0][lp]=a0.x; Ast[kh+1][lp]=a0.y; Ast[kh+2][lp]=a0.z; Ast[kh+3][lp]=a0.w;
        Ast[kh+4][lp]=a1.x; Ast[kh+5][lp]=a1.y; Ast[kh+6][lp]=a1.z; Ast[kh+7][lp]=a1.w;
        ((float4*)&Bs[0][0])[tid] = *(const float4*)(g_w1cat + k0*C_ + tid*4);
        __syncthreads();
        #pragma unroll
        for (int kk = 0; kk < 16; kk++) {
            float4 A0 = *(const float4*)&Ast[kk][ty*8];
            float4 A1 = *(const float4*)&Ast[kk][ty*8+4];
            float4 Bv = *(const float4*)&Bs[kk][tx*4];
            float a[8] = {A0.x,A0.y,A0.z,A0.w,A1.x,A1.y,A1.z,A1.w};
            float bb[4] = {Bv.x,Bv.y,Bv.z,Bv.w};
            #pragma unroll
            for (int i = 0; i < 8; i++)
                #pragma unroll
                for (int j = 0; j < 4; j++)
                    acc[i][j] = fmaf(a[i], bb[j], acc[i][j]);
        }
        __syncthreads();
    }
    // epilogue stage 1: relu + transpose-store H1 into shared
    float swv[8];
    #pragma unroll
    for (int i = 0; i < 8; i++) swv[i] = g_sw[p0 + ty*8 + i];
    #pragma unroll
    for (int j = 0; j < 4; j++) {
        int o = tx*4 + j;
        float bb = g_b1as[o], b2 = g_bb2[o];
        #pragma unroll
        for (int i = 0; i < 8; i++)
            H1T[o][ty*8+i] = fmaxf(acc[i][j] + bb + swv[i]*b2, 0.f);
    }
    __syncthreads();
    float acc2[8][4];
    #pragma unroll
    for (int i = 0; i < 8; i++)
        #pragma unroll
        for (int j = 0; j < 4; j++) acc2[i][j] = 0.f;
    #pragma unroll 8
    for (int kc = 0; kc < 64; kc++) {
        float4 A0 = *(const float4*)&H1T[kc][ty*8];
        float4 A1 = *(const float4*)&H1T[kc][ty*8+4];
        float4 Bv = *(const float4*)(g_w1bT + kc*C_ + tx*4);
        float a[8] = {A0.x,A0.y,A0.z,A0.w,A1.x,A1.y,A1.z,A1.w};
        float bb[4] = {Bv.x,Bv.y,Bv.z,Bv.w};
        #pragma unroll
        for (int i = 0; i < 8; i++)
            #pragma unroll
            for (int j = 0; j < 4; j++)
                acc2[i][j] = fmaf(a[i], bb[j], acc2[i][j]);
    }
    #pragma unroll
    for (int i = 0; i < 8; i++) {
        float* dst = out + (size_t)(p0 + ty*8 + i)*C_ + tx*4;
        #pragma unroll
        for (int j = 0; j < 4; j++) dst[j] = acc2[i][j] + b1b[tx*4+j];
    }
}

// ---------------- launch ----------------
extern "C" void kernel_launch(void* const* d_in, const int* in_sizes, int n_in,
                              void* d_out, int out_size) {
    const float* pcl     = (const float*)d_in[0];
    const float* noise   = (const float*)d_in[1];
    const float* feature = (const float*)d_in[2];
    const float* w2a  = (const float*)d_in[3];
    const float* b2a  = (const float*)d_in[4];
    const float* g2a  = (const float*)d_in[5];
    const float* bt2a = (const float*)d_in[6];
    const float* w2b  = (const float*)d_in[7];
    const float* b2b  = (const float*)d_in[8];
    const float* w1a  = (const float*)d_in[9];
    const float* b1a  = (const float*)d_in[10];
    const float* g1a  = (const float*)d_in[11];
    const float* bt1a = (const float*)d_in[12];
    const float* w1b  = (const float*)d_in[13];
    const float* b1b  = (const float*)d_in[14];
    float* out = (float*)d_out;

    cudaFuncSetAttribute(k_knn, cudaFuncAttributeMaxDynamicSharedMemorySize, M_*16);

    k_prep<<<1, 256>>>(w2a, b2a, g2a, bt2a, b1a, g1a, bt1a, w1b);
    k_prepw<<<96, 256>>>(w2b, w1a, g1a, b2b);
    k_vtab<<<(B_*M_*HID_)/256, 256>>>(pcl);
    k_close<<<512, 256>>>(noise);
    k_knn<<<512, 512, M_*16>>>();
    k_assemble<<<2048, 256>>>(pcl, noise, feature);
    k_gemm<<<128, 256>>>(b1b, out);
}

// round 9
// speedup vs baseline: 2.5729x; 1.1314x over previous
#include <cuda_runtime.h>
#include <cfloat>

#define B_ 2
#define N_ 8192
#define M_ 4096
#define C_ 64
#define HID_ 256
#define KNN_ 15
#define P_ (B_*N_)

// ---------------- scratch (no allocations allowed) ----------------
__device__ float  g_v[B_*M_*HID_];        // 8 MB : W2a'[:, :3] . pcl[m]
__device__ float4 g_pc4[B_*M_];           // (x,y,z,|c|^2) per clean point
__device__ float  g_R[(size_t)P_*HID_];   // 16 MB: weighted relu sums
__device__ float  g_DF[(size_t)P_*128];   // 8 MB : [close_feat | co_feat]
__device__ float  g_sw[P_];               // sum of weights per point
__device__ unsigned long long g_ckey[P_]; // packed (dist,idx) argmin key
__device__ int    g_knn[B_*M_*KNN_];      // 15-NN (self excluded) per clean point
__device__ float  g_w2as[HID_*6];         // BN-folded W2a
__device__ float  g_b2as[HID_];
__device__ float  g_w1cat[384*C_];        // [ W1a'[:, :128] ; W' = w2bT . W1a'[:,128:192] ]
__device__ float  g_bb2[C_];              // b2b . W1a'[:,128:192]
__device__ float  g_b1as[C_];
__device__ float  g_w1bT[C_*C_];          // W1b transposed [k][o]

// ---------------- weight prep: fold BN scale, transpose ----------------
__global__ void k_prep(const float* __restrict__ w2a, const float* __restrict__ b2a,
                       const float* __restrict__ g2a, const float* __restrict__ bt2a,
                       const float* __restrict__ b1a, const float* __restrict__ g1a,
                       const float* __restrict__ bt1a, const float* __restrict__ w1b) {
    int t = threadIdx.x;
    const float sc = rsqrtf(1.0f + 1e-5f);
    if (t < HID_) {
        float s = g2a[t] * sc;
        #pragma unroll
        for (int d = 0; d < 6; d++) g_w2as[t*6+d] = w2a[t*6+d] * s;
        g_b2as[t] = b2a[t] * s + bt2a[t];
    }
    if (t < C_) {
        float s = g1a[t] * sc;
        g_b1as[t] = b1a[t] * s + bt1a[t];
    }
    for (int i = t; i < C_*C_;  i += 256) { int j = i >> 6, o = i & 63; g_w1bT[i] = w1b[o*C_+j]; }
}

// W' fold: g_w1cat[k][o]: k<128 -> W1a'[o][k]; k>=128 -> sum_h w2bT[k-128][h]*W1a'[o][128+h]
__global__ void k_prepw(const float* __restrict__ w2b, const float* __restrict__ w1a,
                        const float* __restrict__ g1a, const float* __restrict__ b2b) {
    int idx = blockIdx.x * 256 + threadIdx.x;      // 384*64 = 24576 -> grid 96
    if (idx >= 384*C_) return;
    int k = idx >> 6, o = idx & 63;
    float s = g1a[o] * rsqrtf(1.0f + 1e-5f);
    float val;
    if (k < 128) val = w1a[o*192 + k] * s;
    else {
        int h = k - 128;
        float acc = 0.f;
        #pragma unroll 8
        for (int o2 = 0; o2 < C_; o2++) acc += w2b[o2*HID_ + h] * w1a[o*192 + 128 + o2];
        val = acc * s;
    }
    g_w1cat[k*C_ + o] = val;
    if (idx < C_) {            // k==0 lane set: bias fold for output o=idx
        float acc = 0.f;
        for (int o2 = 0; o2 < C_; o2++) acc += b2b[o2] * w1a[idx*192 + 128 + o2];
        g_bb2[idx] = acc * s;
    }
}

// ---------------- pc4 + ckey init (no weight dependency) ----------------
__global__ void k_pc4(const float* __restrict__ pcl) {
    int idx = blockIdx.x * 256 + threadIdx.x;          // 16384 threads
    if (idx < B_*M_) {
        float x = pcl[idx*3], y = pcl[idx*3+1], z = pcl[idx*3+2];
        g_pc4[idx] = make_float4(x, y, z, fmaf(x,x, fmaf(y,y, z*z)));
    }
    if (idx < P_) g_ckey[idx] = 0xFFFFFFFFFFFFFFFFull;
}

// ---------------- v table (needs g_w2as) ----------------
__global__ void k_vtab(const float* __restrict__ pcl) {
    int idx = blockIdx.x * blockDim.x + threadIdx.x;   // B*M*HID threads
    if (idx >= B_*M_*HID_) return;
    int pm = idx >> 8, c = idx & 255;
    float x = pcl[pm*3], y = pcl[pm*3+1], z = pcl[pm*3+2];
    g_v[idx] = g_w2as[c*6]*x + g_w2as[c*6+1]*y + g_w2as[c*6+2]*z;
}

// ---------------- nearest clean point: 4 queries/thread, fine-grained grid ----
// grid = 16 query-groups (1024 queries each) x 64 M-chunks (64 cands) = 1024 blocks
#define CLQ_ 4
__global__ void __launch_bounds__(256) k_close(const float* __restrict__ noise) {
    int qg = blockIdx.x >> 6;                  // 16 query groups of 1024
    int ms = blockIdx.x & 63;                  // 64 M-chunks of 64
    int p0 = qg * 1024 + threadIdx.x * CLQ_;
    int b  = p0 >> 13;
    const float4* PC = g_pc4 + b*M_;
    float qx[CLQ_], qy[CLQ_], qz[CLQ_], bd[CLQ_];
    int bi[CLQ_];
    #pragma unroll
    for (int q = 0; q < CLQ_; q++) {
        const float* np = noise + (size_t)(p0+q)*3;
        qx[q] = -2.f*np[0]; qy[q] = -2.f*np[1]; qz[q] = -2.f*np[2];
        bd[q] = FLT_MAX; bi[q] = 0;
    }
    int c0 = ms * 64;
    #pragma unroll 4
    for (int i = 0; i < 64; i++) {
        float4 c = __ldg(&PC[c0 + i]);
        #pragma unroll
        for (int q = 0; q < CLQ_; q++) {
            float d = fmaf(c.x, qx[q], fmaf(c.y, qy[q], fmaf(c.z, qz[q], c.w)));
            if (d < bd[q]) { bd[q] = d; bi[q] = c0 + i; }
        }
    }
    #pragma unroll
    for (int q = 0; q < CLQ_; q++) {
        unsigned u = __float_as_uint(bd[q]);
        u = (u & 0x80000000u) ? ~u : (u | 0x80000000u);   // order-preserving map
        unsigned long long key = ((unsigned long long)u << 32) | (unsigned)bi[q];
        atomicMin(&g_ckey[p0+q], key);
    }
}

// ---------------- 15-NN per clean point: warp-cooperative distributed top-K ----
__global__ void __launch_bounds__(512) k_knn() {
    extern __shared__ float4 sc[];                // 64 KB: whole batch cloud
    int blk  = blockIdx.x;                        // 512 blocks: 256/batch, 16 pts each
    int b    = blk >> 8;
    int w    = threadIdx.x >> 5;
    int lane = threadIdx.x & 31;
    int m    = (blk & 255) * 16 + w;
    const float4* PC = g_pc4 + b*M_;
    for (int i = threadIdx.x; i < M_; i += 512) sc[i] = PC[i];
    __syncthreads();
    float4 qc = sc[m];
    float qx = -2.f*qc.x, qy = -2.f*qc.y, qz = -2.f*qc.z;
    float Dl = FLT_MAX;                           // list entry held by this lane
    int   Il = -1;
    float worst = FLT_MAX;                        // warp-uniform 15th best
    for (int t0 = 0; t0 < M_; t0 += 32) {
        int c = t0 + lane;
        float4 cc = sc[c];
        float d = fmaf(cc.x, qx, fmaf(cc.y, qy, fmaf(cc.z, qz, cc.w)));
        bool pass = (d < worst) & (c != m);
        unsigned mask = __ballot_sync(0xffffffffu, pass);
        while (mask) {                            // warp-uniform loop
            int s = __ffs(mask) - 1;
            mask &= mask - 1;
            float bd = __shfl_sync(0xffffffffu, d, s);
            int   bix = t0 + s;
            if (bd < worst) {                     // warp-uniform condition
                float pd = __shfl_up_sync(0xffffffffu, Dl, 1);
                int   pi = __shfl_up_sync(0xffffffffu, Il, 1);
                if (lane == 0) { pd = -FLT_MAX; pi = -1; }
                if (lane < KNN_ && Dl >= bd) {
                    if (pd >= bd) { Dl = pd; Il = pi; }
                    else          { Dl = bd; Il = bix; }
                }
                worst = __shfl_sync(0xffffffffu, Dl, KNN_ - 1);
            }
        }
    }
    if (lane < KNN_) g_knn[(b*M_+m)*KNN_ + lane] = Il;
}

// ---------------- assemble: weights, weighted relu sums R, df[0:128] ----------------
__global__ void __launch_bounds__(256) k_assemble(const float* __restrict__ pcl,
                                                  const float* __restrict__ noise,
                                                  const float* __restrict__ feature) {
    int w = threadIdx.x >> 5, lane = threadIdx.x & 31;
    int p = blockIdx.x * 8 + w;           // warp per noisy point
    int b = p >> 13;                      // N = 8192
    int m0 = (int)(g_ckey[p] & 0xFFFFFFFFull);
    const float* PB = pcl + b*M_*3;
    const float* FB = feature + b*M_*C_;
    float nx = noise[p*3], ny = noise[p*3+1], nz = noise[p*3+2];
    float cx = PB[m0*3], cy = PB[m0*3+1], cz = PB[m0*3+2];
    float t[8], r[8];
    #pragma unroll
    for (int j = 0; j < 8; j++) {
        int c = lane + 32*j;
        const float* wv = g_w2as + c*6;
        t[j] = g_b2as[c] + wv[3]*cx + wv[4]*cy + wv[5]*cz
                         - (wv[0]*nx + wv[1]*ny + wv[2]*nz);
        r[j] = 0.f;
    }
    float S = 0.f, co0 = 0.f, co1 = 0.f;
    const int* nbp = g_knn + (b*M_+m0)*KNN_;
    #pragma unroll 1
    for (int k = 0; k < KNN_; k++) {
        int nb = nbp[k];
        float dx = PB[nb*3]-nx, dy = PB[nb*3+1]-ny, dz = PB[nb*3+2]-nz;
        float dst = sqrtf(fmaf(dx, dx, fmaf(dy, dy, dz*dz)));
        float e = __expf(-10.f * dst);
        S += e;
        const float* vr = g_v + (nb + b*M_)*HID_;
        #pragma unroll
        for (int j = 0; j < 8; j++) {
            float h = vr[lane + 32*j] + t[j];
            r[j] = fmaf(e, fmaxf(h, 0.f), r[j]);
        }
        co0 = fmaf(e, FB[nb*C_+lane],    co0);
        co1 = fmaf(e, FB[nb*C_+32+lane], co1);
    }
    float inv = 1.f / (S + 1e-7f);
    float* Rr = g_R + (size_t)p*HID_;
    #pragma unroll
    for (int j = 0; j < 8; j++) Rr[lane + 32*j] = r[j] * inv;
    float* dfp = g_DF + (size_t)p*128;
    dfp[lane]       = FB[m0*C_+lane];
    dfp[32+lane]    = FB[m0*C_+32+lane];
    dfp[64+lane]    = co0 * inv;
    dfp[96+lane]    = co1 * inv;
    if (lane == 0) g_sw[p] = S * inv;
}

// ---------------- fused GEMM: H1 = relu([DF|R].w1cat + b1as + sw*bb2); out = H1.w1bT + b1b
__global__ void __launch_bounds__(256) k_gemm(const float* __restrict__ b1b,
                                              float* __restrict__ out) {
    __shared__ __align__(16) float Ast[16][132];
    __shared__ __align__(16) float Bs[16][64];
    __shared__ __align__(16) float H1T[64][136];
    int tid = threadIdx.x;
    int p0 = blockIdx.x * 128;
    int ty = tid >> 4, tx = tid & 15;
    int lp = tid >> 1, kh = (tid & 1) * 8;
    float acc[8][4];
    #pragma unroll
    for (int i = 0; i < 8; i++)
        #pragma unroll
        for (int j = 0; j < 4; j++) acc[i][j] = 0.f;
    for (int k0 = 0; k0 < 384; k0 += 16) {
        const float* ap = (k0 < 128)
            ? g_DF + (size_t)(p0+lp)*128 + k0 + kh
            : g_R  + (size_t)(p0+lp)*HID_ + (k0 - 128) + kh;
        float4 a0 = *(const float4*)ap;
        float4 a1 = *(const float4*)(ap + 4);
        Ast[kh+0][lp]=a0.x; Ast[kh+1][lp]=a0.y; Ast[kh+2][lp]=a0.z; Ast[kh+3][lp]=a0.w;
        Ast[kh+4][lp]=a1.x; Ast[kh+5][lp]=a1.y; Ast[kh+6][lp]=a1.z; Ast[kh+7][lp]=a1.w;
        ((float4*)&Bs[0][0])[tid] = *(const float4*)(g_w1cat + k0*C_ + tid*4);
        __syncthreads();
        #pragma unroll
        for (int kk = 0; kk < 16; kk++) {
            float4 A0 = *(const float4*)&Ast[kk][ty*8];
            float4 A1 = *(const float4*)&Ast[kk][ty*8+4];
            float4 Bv = *(const float4*)&Bs[kk][tx*4];
            float a[8] = {A0.x,A0.y,A0.z,A0.w,A1.x,A1.y,A1.z,A1.w};
            float bb[4] = {Bv.x,Bv.y,Bv.z,Bv.w};
            #pragma unroll
            for (int i = 0; i < 8; i++)
                #pragma unroll
                for (int j = 0; j < 4; j++)
                    acc[i][j] = fmaf(a[i], bb[j], acc[i][j]);
        }
        __syncthreads();
    }
    // epilogue stage 1: relu + transpose-store H1 into shared
    float swv[8];
    #pragma unroll
    for (int i = 0; i < 8; i++) swv[i] = g_sw[p0 + ty*8 + i];
    #pragma unroll
    for (int j = 0; j < 4; j++) {
        int o = tx*4 + j;
        float bb = g_b1as[o], b2 = g_bb2[o];
        #pragma unroll
        for (int i = 0; i < 8; i++)
            H1T[o][ty*8+i] = fmaxf(acc[i][j] + bb + swv[i]*b2, 0.f);
    }
    __syncthreads();
    float acc2[8][4];
    #pragma unroll
    for (int i = 0; i < 8; i++)
        #pragma unroll
        for (int j = 0; j < 4; j++) acc2[i][j] = 0.f;
    #pragma unroll 8
    for (int kc = 0; kc < 64; kc++) {
        float4 A0 = *(const float4*)&H1T[kc][ty*8];
        float4 A1 = *(const float4*)&H1T[kc][ty*8+4];
        float4 Bv = *(const float4*)(g_w1bT + kc*C_ + tx*4);
        float a[8] = {A0.x,A0.y,A0.z,A0.w,A1.x,A1.y,A1.z,A1.w};
        float bb[4] = {Bv.x,Bv.y,Bv.z,Bv.w};
        #pragma unroll
        for (int i = 0; i < 8; i++)
            #pragma unroll
            for (int j = 0; j < 4; j++)
                acc2[i][j] = fmaf(a[i], bb[j], acc2[i][j]);
    }
    #pragma unroll
    for (int i = 0; i < 8; i++) {
        float* dst = out + (size_t)(p0 + ty*8 + i)*C_ + tx*4;
        #pragma unroll
        for (int j = 0; j < 4; j++) dst[j] = acc2[i][j] + b1b[tx*4+j];
    }
}

// ---------------- launch ----------------
extern "C" void kernel_launch(void* const* d_in, const int* in_sizes, int n_in,
                              void* d_out, int out_size) {
    const float* pcl     = (const float*)d_in[0];
    const float* noise   = (const float*)d_in[1];
    const float* feature = (const float*)d_in[2];
    const float* w2a  = (const float*)d_in[3];
    const float* b2a  = (const float*)d_in[4];
    const float* g2a  = (const float*)d_in[5];
    const float* bt2a = (const float*)d_in[6];
    const float* w2b  = (const float*)d_in[7];
    const float* b2b  = (const float*)d_in[8];
    const float* w1a  = (const float*)d_in[9];
    const float* b1a  = (const float*)d_in[10];
    const float* g1a  = (const float*)d_in[11];
    const float* bt1a = (const float*)d_in[12];
    const float* w1b  = (const float*)d_in[13];
    const float* b1b  = (const float*)d_in[14];
    float* out = (float*)d_out;

    // one-time infra (first call is the non-captured correctness run)
    static cudaStream_t s1 = 0;
    static cudaEvent_t  e_fork = 0, e_join = 0;
    static bool infra_ok = false;
    static bool tried = false;
    if (!tried) {
        tried = true;
        infra_ok = (cudaStreamCreateWithFlags(&s1, cudaStreamNonBlocking) == cudaSuccess)
                && (cudaEventCreateWithFlags(&e_fork, cudaEventDisableTiming) == cudaSuccess)
                && (cudaEventCreateWithFlags(&e_join, cudaEventDisableTiming) == cudaSuccess);
        cudaFuncSetAttribute(k_knn, cudaFuncAttributeMaxDynamicSharedMemorySize, M_*16);
    }

    k_pc4<<<64, 256>>>(pcl);
    if (infra_ok) {
        cudaEventRecord(e_fork, 0);
        cudaStreamWaitEvent(s1, e_fork, 0);
        k_knn<<<512, 512, M_*16, s1>>>();
        k_prep<<<1, 256>>>(w2a, b2a, g2a, bt2a, b1a, g1a, bt1a, w1b);
        k_prepw<<<96, 256>>>(w2b, w1a, g1a, b2b);
        k_vtab<<<(B_*M_*HID_)/256, 256>>>(pcl);
        k_close<<<1024, 256>>>(noise);
        cudaEventRecord(e_join, s1);
        cudaStreamWaitEvent(0, e_join, 0);
    } else {
        k_knn<<<512, 512, M_*16>>>();
        k_prep<<<1, 256>>>(w2a, b2a, g2a, bt2a, b1a, g1a, bt1a, w1b);
        k_prepw<<<96, 256>>>(w2b, w1a, g1a, b2b);
        k_vtab<<<(B_*M_*HID_)/256, 256>>>(pcl);
        k_close<<<1024, 256>>>(noise);
    }
    k_assemble<<<2048, 256>>>(pcl, noise, feature);
    k_gemm<<<128, 256>>>(b1b, out);
}

// round 10
// speedup vs baseline: 2.7196x; 1.0570x over previous
#include <cuda_runtime.h>
#include <cfloat>

#define B_ 2
#define N_ 8192
#define M_ 4096
#define C_ 64
#define HID_ 256
#define KNN_ 15
#define P_ (B_*N_)

// ---------------- scratch (no allocations allowed) ----------------
__device__ float  g_v[B_*M_*HID_];        // 8 MB : W2a'[:, :3] . pcl[m]
__device__ float4 g_pc4[B_*M_];           // (x,y,z,|c|^2) per clean point
__device__ float  g_R[(size_t)P_*HID_];   // 16 MB: weighted relu sums
__device__ float  g_DF[(size_t)P_*128];   // 8 MB : [close_feat | co_feat]
__device__ float  g_sw[P_];               // sum of weights per point
__device__ unsigned long long g_ckey[P_]; // packed (dist,idx) argmin key
__device__ int    g_knn[B_*M_*KNN_];      // 15-NN (self excluded) per clean point
__device__ float  g_w2as[HID_*6];         // BN-folded W2a
__device__ float  g_b2as[HID_];
__device__ float  g_w1cat[384*C_];        // [ W1a'[:, :128] ; W' = w2bT . W1a'[:,128:192] ]
__device__ float  g_bb2[C_];              // b2b . W1a'[:,128:192]
__device__ float  g_b1as[C_];
__device__ float  g_w1bT[C_*C_];          // W1b transposed [k][o]

// ---------------- weight prep: fold BN scale, transpose ----------------
__global__ void k_prep(const float* __restrict__ w2a, const float* __restrict__ b2a,
                       const float* __restrict__ g2a, const float* __restrict__ bt2a,
                       const float* __restrict__ b1a, const float* __restrict__ g1a,
                       const float* __restrict__ bt1a, const float* __restrict__ w1b) {
    int t = threadIdx.x;
    const float sc = rsqrtf(1.0f + 1e-5f);
    if (blockIdx.x == 0) {
        if (t < HID_) {
            float s = g2a[t] * sc;
            #pragma unroll
            for (int d = 0; d < 6; d++) g_w2as[t*6+d] = w2a[t*6+d] * s;
            g_b2as[t] = b2a[t] * s + bt2a[t];
        }
        if (t < C_) {
            float s = g1a[t] * sc;
            g_b1as[t] = b1a[t] * s + bt1a[t];
        }
    } else {
        int i = (blockIdx.x - 1) * 256 + t;            // 16 blocks cover 4096
        if (i < C_*C_) { int j = i >> 6, o = i & 63; g_w1bT[i] = w1b[o*C_+j]; }
    }
}

// W' fold, coalesced: block = output col o, thread = hidden h.
// g_w1cat[k][o]: k<128 -> W1a'[o][k]; k>=128 -> sum_o2 w2b[o2][k-128]*W1a'[o][128+o2]
__global__ void __launch_bounds__(256) k_prepw(const float* __restrict__ w2b,
                                               const float* __restrict__ w1a,
                                               const float* __restrict__ g1a,
                                               const float* __restrict__ b2b) {
    __shared__ float wa[C_];
    int o = blockIdx.x;                     // 64 blocks
    int h = threadIdx.x;                    // 256 threads
    float s = g1a[o] * rsqrtf(1.0f + 1e-5f);
    if (h < C_) wa[h] = w1a[o*192 + 128 + h];
    if (h < 128) g_w1cat[h*C_ + o] = w1a[o*192 + h] * s;
    __syncthreads();
    float acc = 0.f;
    #pragma unroll 8
    for (int o2 = 0; o2 < C_; o2++)
        acc = fmaf(__ldg(&w2b[o2*HID_ + h]), wa[o2], acc);   // coalesced across h
    g_w1cat[(128 + h)*C_ + o] = acc * s;
    if (h == 0) {
        float a = 0.f;
        for (int o2 = 0; o2 < C_; o2++) a = fmaf(b2b[o2], wa[o2], a);
        g_bb2[o] = a * s;
    }
}

// ---------------- pc4 + ckey init (no weight dependency) ----------------
__global__ void k_pc4(const float* __restrict__ pcl) {
    int idx = blockIdx.x * 256 + threadIdx.x;          // 16384 threads
    if (idx < B_*M_) {
        float x = pcl[idx*3], y = pcl[idx*3+1], z = pcl[idx*3+2];
        g_pc4[idx] = make_float4(x, y, z, fmaf(x,x, fmaf(y,y, z*z)));
    }
    if (idx < P_) g_ckey[idx] = 0xFFFFFFFFFFFFFFFFull;
}

// ---------------- v table (needs g_w2as) ----------------
__global__ void k_vtab(const float* __restrict__ pcl) {
    int idx = blockIdx.x * blockDim.x + threadIdx.x;   // B*M*HID threads
    if (idx >= B_*M_*HID_) return;
    int pm = idx >> 8, c = idx & 255;
    float x = pcl[pm*3], y = pcl[pm*3+1], z = pcl[pm*3+2];
    g_v[idx] = g_w2as[c*6]*x + g_w2as[c*6+1]*y + g_w2as[c*6+2]*z;
}

// ---------------- nearest clean point: 4 queries/thread, fine-grained grid ----
// grid = 16 query-groups (1024 queries each) x 64 M-chunks (64 cands) = 1024 blocks
#define CLQ_ 4
__global__ void __launch_bounds__(256) k_close(const float* __restrict__ noise) {
    int qg = blockIdx.x >> 6;                  // 16 query groups of 1024
    int ms = blockIdx.x & 63;                  // 64 M-chunks of 64
    int p0 = qg * 1024 + threadIdx.x * CLQ_;
    int b  = p0 >> 13;
    const float4* PC = g_pc4 + b*M_;
    float qx[CLQ_], qy[CLQ_], qz[CLQ_], bd[CLQ_];
    int bi[CLQ_];
    #pragma unroll
    for (int q = 0; q < CLQ_; q++) {
        const float* np = noise + (size_t)(p0+q)*3;
        qx[q] = -2.f*np[0]; qy[q] = -2.f*np[1]; qz[q] = -2.f*np[2];
        bd[q] = FLT_MAX; bi[q] = 0;
    }
    int c0 = ms * 64;
    #pragma unroll 4
    for (int i = 0; i < 64; i++) {
        float4 c = __ldg(&PC[c0 + i]);
        #pragma unroll
        for (int q = 0; q < CLQ_; q++) {
            float d = fmaf(c.x, qx[q], fmaf(c.y, qy[q], fmaf(c.z, qz[q], c.w)));
            if (d < bd[q]) { bd[q] = d; bi[q] = c0 + i; }
        }
    }
    #pragma unroll
    for (int q = 0; q < CLQ_; q++) {
        unsigned u = __float_as_uint(bd[q]);
        u = (u & 0x80000000u) ? ~u : (u | 0x80000000u);   // order-preserving map
        unsigned long long key = ((unsigned long long)u << 32) | (unsigned)bi[q];
        atomicMin(&g_ckey[p0+q], key);
    }
}

// ---------------- 15-NN per clean point: warp-cooperative distributed top-K ----
__global__ void __launch_bounds__(512) k_knn() {
    extern __shared__ float4 sc[];                // 64 KB: whole batch cloud
    int blk  = blockIdx.x;                        // 512 blocks: 256/batch, 16 pts each
    int b    = blk >> 8;
    int w    = threadIdx.x >> 5;
    int lane = threadIdx.x & 31;
    int m    = (blk & 255) * 16 + w;
    const float4* PC = g_pc4 + b*M_;
    for (int i = threadIdx.x; i < M_; i += 512) sc[i] = PC[i];
    __syncthreads();
    float4 qc = sc[m];
    float qx = -2.f*qc.x, qy = -2.f*qc.y, qz = -2.f*qc.z;
    float Dl = FLT_MAX;                           // list entry held by this lane
    int   Il = -1;
    float worst = FLT_MAX;                        // warp-uniform 15th best
    for (int t0 = 0; t0 < M_; t0 += 32) {
        int c = t0 + lane;
        float4 cc = sc[c];
        float d = fmaf(cc.x, qx, fmaf(cc.y, qy, fmaf(cc.z, qz, cc.w)));
        bool pass = (d < worst) & (c != m);
        unsigned mask = __ballot_sync(0xffffffffu, pass);
        while (mask) {                            // warp-uniform loop
            int s = __ffs(mask) - 1;
            mask &= mask - 1;
            float bd = __shfl_sync(0xffffffffu, d, s);
            int   bix = t0 + s;
            if (bd < worst) {                     // warp-uniform condition
                float pd = __shfl_up_sync(0xffffffffu, Dl, 1);
                int   pi = __shfl_up_sync(0xffffffffu, Il, 1);
                if (lane == 0) { pd = -FLT_MAX; pi = -1; }
                if (lane < KNN_ && Dl >= bd) {
                    if (pd >= bd) { Dl = pd; Il = pi; }
                    else          { Dl = bd; Il = bix; }
                }
                worst = __shfl_sync(0xffffffffu, Dl, KNN_ - 1);
            }
        }
    }
    if (lane < KNN_) g_knn[(b*M_+m)*KNN_ + lane] = Il;
}

// ---------------- assemble: weights, weighted relu sums R, df[0:128] ----------------
__global__ void __launch_bounds__(256) k_assemble(const float* __restrict__ pcl,
                                                  const float* __restrict__ noise,
                                                  const float* __restrict__ feature) {
    int w = threadIdx.x >> 5, lane = threadIdx.x & 31;
    int p = blockIdx.x * 8 + w;           // warp per noisy point
    int b = p >> 13;                      // N = 8192
    int m0 = (int)(g_ckey[p] & 0xFFFFFFFFull);
    const float* PB = pcl + b*M_*3;
    const float* FB = feature + b*M_*C_;
    float nx = noise[p*3], ny = noise[p*3+1], nz = noise[p*3+2];
    float cx = PB[m0*3], cy = PB[m0*3+1], cz = PB[m0*3+2];
    float t[8], r[8];
    #pragma unroll
    for (int j = 0; j < 8; j++) {
        int c = lane + 32*j;
        const float* wv = g_w2as + c*6;
        t[j] = g_b2as[c] + wv[3]*cx + wv[4]*cy + wv[5]*cz
                         - (wv[0]*nx + wv[1]*ny + wv[2]*nz);
        r[j] = 0.f;
    }
    float S = 0.f, co0 = 0.f, co1 = 0.f;
    const int* nbp = g_knn + (b*M_+m0)*KNN_;
    #pragma unroll 1
    for (int k = 0; k < KNN_; k++) {
        int nb = nbp[k];
        float dx = PB[nb*3]-nx, dy = PB[nb*3+1]-ny, dz = PB[nb*3+2]-nz;
        float dst = sqrtf(fmaf(dx, dx, fmaf(dy, dy, dz*dz)));
        float e = __expf(-10.f * dst);
        S += e;
        const float* vr = g_v + (nb + b*M_)*HID_;
        #pragma unroll
        for (int j = 0; j < 8; j++) {
            float h = vr[lane + 32*j] + t[j];
            r[j] = fmaf(e, fmaxf(h, 0.f), r[j]);
        }
        co0 = fmaf(e, FB[nb*C_+lane],    co0);
        co1 = fmaf(e, FB[nb*C_+32+lane], co1);
    }
    float inv = 1.f / (S + 1e-7f);
    float* Rr = g_R + (size_t)p*HID_;
    #pragma unroll
    for (int j = 0; j < 8; j++) Rr[lane + 32*j] = r[j] * inv;
    float* dfp = g_DF + (size_t)p*128;
    dfp[lane]       = FB[m0*C_+lane];
    dfp[32+lane]    = FB[m0*C_+32+lane];
    dfp[64+lane]    = co0 * inv;
    dfp[96+lane]    = co1 * inv;
    if (lane == 0) g_sw[p] = S * inv;
}

// ---------------- fused GEMM: H1 = relu([DF|R].w1cat + b1as + sw*bb2); out = H1.w1bT + b1b
__global__ void __launch_bounds__(256) k_gemm(const float* __restrict__ b1b,
                                              float* __restrict__ out) {
    __shared__ __align__(16) float Ast[16][132];
    __shared__ __align__(16) float Bs[16][64];
    __shared__ __align__(16) float H1T[64][136];
    int tid = threadIdx.x;
    int p0 = blockIdx.x * 128;
    int ty = tid >> 4, tx = tid & 15;
    int lp = tid >> 1, kh = (tid & 1) * 8;
    float acc[8][4];
    #pragma unroll
    for (int i = 0; i < 8; i++)
        #pragma unroll
        for (int j = 0; j < 4; j++) acc[i][j] = 0.f;
    for (int k0 = 0; k0 < 384; k0 += 16) {
        const float* ap = (k0 < 128)
            ? g_DF + (size_t)(p0+lp)*128 + k0 + kh
            : g_R  + (size_t)(p0+lp)*HID_ + (k0 - 128) + kh;
        float4 a0 = *(const float4*)ap;
        float4 a1 = *(const float4*)(ap + 4);
        Ast[kh+0][lp]=a0.x; Ast[kh+1][lp]=a0.y; Ast[kh+2][lp]=a0.z; Ast[kh+3][lp]=a0.w;
        Ast[kh+4][lp]=a1.x; Ast[kh+5][lp]=a1.y; Ast[kh+6][lp]=a1.z; Ast[kh+7][lp]=a1.w;
        ((float4*)&Bs[0][0])[tid] = *(const float4*)(g_w1cat + k0*C_ + tid*4);
        __syncthreads();
        #pragma unroll
        for (int kk = 0; kk < 16; kk++) {
            float4 A0 = *(const float4*)&Ast[kk][ty*8];
            float4 A1 = *(const float4*)&Ast[kk][ty*8+4];
            float4 Bv = *(const float4*)&Bs[kk][tx*4];
            float a[8] = {A0.x,A0.y,A0.z,A0.w,A1.x,A1.y,A1.z,A1.w};
            float bb[4] = {Bv.x,Bv.y,Bv.z,Bv.w};
            #pragma unroll
            for (int i = 0; i < 8; i++)
                #pragma unroll
                for (int j = 0; j < 4; j++)
                    acc[i][j] = fmaf(a[i], bb[j], acc[i][j]);
        }
        __syncthreads();
    }
    // epilogue stage 1: relu + transpose-store H1 into shared
    float swv[8];
    #pragma unroll
    for (int i = 0; i < 8; i++) swv[i] = g_sw[p0 + ty*8 + i];
    #pragma unroll
    for (int j = 0; j < 4; j++) {
        int o = tx*4 + j;
        float bb = g_b1as[o], b2 = g_bb2[o];
        #pragma unroll
        for (int i = 0; i < 8; i++)
            H1T[o][ty*8+i] = fmaxf(acc[i][j] + bb + swv[i]*b2, 0.f);
    }
    __syncthreads();
    float acc2[8][4];
    #pragma unroll
    for (int i = 0; i < 8; i++)
        #pragma unroll
        for (int j = 0; j < 4; j++) acc2[i][j] = 0.f;
    #pragma unroll 8
    for (int kc = 0; kc < 64; kc++) {
        float4 A0 = *(const float4*)&H1T[kc][ty*8];
        float4 A1 = *(const float4*)&H1T[kc][ty*8+4];
        float4 Bv = *(const float4*)(g_w1bT + kc*C_ + tx*4);
        float a[8] = {A0.x,A0.y,A0.z,A0.w,A1.x,A1.y,A1.z,A1.w};
        float bb[4] = {Bv.x,Bv.y,Bv.z,Bv.w};
        #pragma unroll
        for (int i = 0; i < 8; i++)
            #pragma unroll
            for (int j = 0; j < 4; j++)
                acc2[i][j] = fmaf(a[i], bb[j], acc2[i][j]);
    }
    #pragma unroll
    for (int i = 0; i < 8; i++) {
        float* dst = out + (size_t)(p0 + ty*8 + i)*C_ + tx*4;
        #pragma unroll
        for (int j = 0; j < 4; j++) dst[j] = acc2[i][j] + b1b[tx*4+j];
    }
}

// ---------------- launch ----------------
extern "C" void kernel_launch(void* const* d_in, const int* in_sizes, int n_in,
                              void* d_out, int out_size) {
    const float* pcl     = (const float*)d_in[0];
    const float* noise   = (const float*)d_in[1];
    const float* feature = (const float*)d_in[2];
    const float* w2a  = (const float*)d_in[3];
    const float* b2a  = (const float*)d_in[4];
    const float* g2a  = (const float*)d_in[5];
    const float* bt2a = (const float*)d_in[6];
    const float* w2b  = (const float*)d_in[7];
    const float* b2b  = (const float*)d_in[8];
    const float* w1a  = (const float*)d_in[9];
    const float* b1a  = (const float*)d_in[10];
    const float* g1a  = (const float*)d_in[11];
    const float* bt1a = (const float*)d_in[12];
    const float* w1b  = (const float*)d_in[13];
    const float* b1b  = (const float*)d_in[14];
    float* out = (float*)d_out;

    // one-time infra (first call is the non-captured correctness run)
    static cudaStream_t s1 = 0, s2 = 0;
    static cudaEvent_t  e0 = 0, e1 = 0, e2 = 0, e3 = 0;
    static bool infra_ok = false;
    static bool tried = false;
    if (!tried) {
        tried = true;
        infra_ok = (cudaStreamCreateWithFlags(&s1, cudaStreamNonBlocking) == cudaSuccess)
                && (cudaStreamCreateWithFlags(&s2, cudaStreamNonBlocking) == cudaSuccess)
                && (cudaEventCreateWithFlags(&e0, cudaEventDisableTiming) == cudaSuccess)
                && (cudaEventCreateWithFlags(&e1, cudaEventDisableTiming) == cudaSuccess)
                && (cudaEventCreateWithFlags(&e2, cudaEventDisableTiming) == cudaSuccess)
                && (cudaEventCreateWithFlags(&e3, cudaEventDisableTiming) == cudaSuccess);
        cudaFuncSetAttribute(k_knn, cudaFuncAttributeMaxDynamicSharedMemorySize, M_*16);
    }

    if (infra_ok) {
        // s2: prepw (no deps, needed only by gemm)
        cudaEventRecord(e0, 0);
        cudaStreamWaitEvent(s2, e0, 0);
        k_prepw<<<64, 256, 0, s2>>>(w2b, w1a, g1a, b2b);
        // s0: pc4, then fork knn to s1
        k_pc4<<<64, 256>>>(pcl);
        cudaEventRecord(e1, 0);
        cudaStreamWaitEvent(s1, e1, 0);
        k_knn<<<512, 512, M_*16, s1>>>();
        // s0 leg: close (no weight dep) + prep + vtab
        k_close<<<1024, 256>>>(noise);
        k_prep<<<17, 256>>>(w2a, b2a, g2a, bt2a, b1a, g1a, bt1a, w1b);
        k_vtab<<<(B_*M_*HID_)/256, 256>>>(pcl);
        // join knn before assemble
        cudaEventRecord(e2, s1);
        cudaStreamWaitEvent(0, e2, 0);
        k_assemble<<<2048, 256>>>(pcl, noise, feature);
        // join prepw before gemm
        cudaEventRecord(e3, s2);
        cudaStreamWaitEvent(0, e3, 0);
        k_gemm<<<128, 256>>>(b1b, out);
    } else {
        k_prepw<<<64, 256>>>(w2b, w1a, g1a, b2b);
        k_pc4<<<64, 256>>>(pcl);
        k_knn<<<512, 512, M_*16>>>();
        k_close<<<1024, 256>>>(noise);
        k_prep<<<17, 256>>>(w2a, b2a, g2a, bt2a, b1a, g1a, bt1a, w1b);
        k_vtab<<<(B_*M_*HID_)/256, 256>>>(pcl);
        k_assemble<<<2048, 256>>>(pcl, noise, feature);
        k_gemm<<<128, 256>>>(b1b, out);
    }
}

// round 13
// speedup vs baseline: 2.8313x; 1.0411x over previous
#include <cuda_runtime.h>
#include <cfloat>
#include <cstdint>

#define B_ 2
#define N_ 8192
#define M_ 4096
#define C_ 64
#define HID_ 256
#define KNN_ 15
#define P_ (B_*N_)

// ---------------- scratch (no allocations allowed) ----------------
__device__ float  g_v[B_*M_*HID_];        // 8 MB : W2a'[:, :3] . pcl[m]
__device__ float4 g_pc4[B_*M_];           // (x,y,z,|c|^2) per clean point
__device__ float  g_R[(size_t)P_*HID_];   // 16 MB: weighted relu sums
__device__ float  g_DF[(size_t)P_*128];   // 8 MB : [close_feat | co_feat]
__device__ float  g_sw[P_];               // sum of weights per point
__device__ unsigned long long g_ckey[P_]; // packed (dist,idx) argmin key
__device__ int    g_knn[B_*M_*KNN_];      // 15-NN (self excluded) per clean point
__device__ float  g_w2as[HID_*6];         // BN-folded W2a
__device__ float  g_b2as[HID_];
__device__ float  g_w1hi[384*C_];         // tf32-hi of fused stage-1 B matrix [k][o]
__device__ float  g_w1lo[384*C_];         // tf32-lo residual
__device__ float  g_bb2[C_];              // b2b . W1a'[:,128:192]
__device__ float  g_b1as[C_];
__device__ float  g_w1bT[C_*C_];          // W1b transposed [k][o]

__device__ __forceinline__ float tf32_hi(float a) {
    uint32_t u;
    asm("cvt.rna.tf32.f32 %0, %1;" : "=r"(u) : "f"(a));
    return __uint_as_float(u);
}

__device__ __forceinline__ void mma_tf32(float* d, uint32_t a0, uint32_t a1,
                                         uint32_t a2, uint32_t a3,
                                         uint32_t b0, uint32_t b1) {
    asm volatile("mma.sync.aligned.m16n8k8.row.col.f32.tf32.tf32.f32 "
                 "{%0,%1,%2,%3}, {%4,%5,%6,%7}, {%8,%9}, {%0,%1,%2,%3};\n"
                 : "+f"(d[0]), "+f"(d[1]), "+f"(d[2]), "+f"(d[3])
                 : "r"(a0), "r"(a1), "r"(a2), "r"(a3), "r"(b0), "r"(b1));
}

// ---------------- weight prep: fold BN scale, transpose ----------------
__global__ void k_prep(const float* __restrict__ w2a, const float* __restrict__ b2a,
                       const float* __restrict__ g2a, const float* __restrict__ bt2a,
                       const float* __restrict__ b1a, const float* __restrict__ g1a,
                       const float* __restrict__ bt1a, const float* __restrict__ w1b) {
    int t = threadIdx.x;
    const float sc = rsqrtf(1.0f + 1e-5f);
    if (blockIdx.x == 0) {
        if (t < HID_) {
            float s = g2a[t] * sc;
            #pragma unroll
            for (int d = 0; d < 6; d++) g_w2as[t*6+d] = w2a[t*6+d] * s;
            g_b2as[t] = b2a[t] * s + bt2a[t];
        }
        if (t < C_) {
            float s = g1a[t] * sc;
            g_b1as[t] = b1a[t] * s + bt1a[t];
        }
    } else {
        int i = (blockIdx.x - 1) * 256 + t;            // 16 blocks cover 4096
        if (i < C_*C_) { int j = i >> 6, o = i & 63; g_w1bT[i] = w1b[o*C_+j]; }
    }
}

// W' fold, coalesced + tf32 hi/lo split.
// stage1 B[k][o]: k<128 -> W1a'[o][k]; k>=128 -> sum_o2 w2b[o2][k-128]*W1a'[o][128+o2]
__global__ void __launch_bounds__(256) k_prepw(const float* __restrict__ w2b,
                                               const float* __restrict__ w1a,
                                               const float* __restrict__ g1a,
                                               const float* __restrict__ b2b) {
    __shared__ float wa[C_];
    int o = blockIdx.x;                     // 64 blocks
    int h = threadIdx.x;                    // 256 threads
    float s = g1a[o] * rsqrtf(1.0f + 1e-5f);
    if (h < C_) wa[h] = w1a[o*192 + 128 + h];
    if (h < 128) {
        float v = w1a[o*192 + h] * s;
        float hi = tf32_hi(v);
        g_w1hi[h*C_ + o] = hi;
        g_w1lo[h*C_ + o] = tf32_hi(v - hi);
    }
    __syncthreads();
    float acc = 0.f;
    #pragma unroll 8
    for (int o2 = 0; o2 < C_; o2++)
        acc = fmaf(__ldg(&w2b[o2*HID_ + h]), wa[o2], acc);   // coalesced across h
    float v = acc * s;
    float hi = tf32_hi(v);
    g_w1hi[(128 + h)*C_ + o] = hi;
    g_w1lo[(128 + h)*C_ + o] = tf32_hi(v - hi);
    if (h == 0) {
        float a = 0.f;
        for (int o2 = 0; o2 < C_; o2++) a = fmaf(b2b[o2], wa[o2], a);
        g_bb2[o] = a * s;
    }
}

// ---------------- pc4 + ckey init (no weight dependency) ----------------
__global__ void k_pc4(const float* __restrict__ pcl) {
    int idx = blockIdx.x * 256 + threadIdx.x;          // 16384 threads
    if (idx < B_*M_) {
        float x = pcl[idx*3], y = pcl[idx*3+1], z = pcl[idx*3+2];
        g_pc4[idx] = make_float4(x, y, z, fmaf(x,x, fmaf(y,y, z*z)));
    }
    if (idx < P_) g_ckey[idx] = 0xFFFFFFFFFFFFFFFFull;
}

// ---------------- v table (needs g_w2as) ----------------
__global__ void k_vtab(const float* __restrict__ pcl) {
    int idx = blockIdx.x * blockDim.x + threadIdx.x;   // B*M*HID threads
    if (idx >= B_*M_*HID_) return;
    int pm = idx >> 8, c = idx & 255;
    float x = pcl[pm*3], y = pcl[pm*3+1], z = pcl[pm*3+2];
    g_v[idx] = g_w2as[c*6]*x + g_w2as[c*6+1]*y + g_w2as[c*6+2]*z;
}

// ---------------- nearest clean point: 4 queries/thread, fine-grained grid ----
#define CLQ_ 4
__global__ void __launch_bounds__(256) k_close(const float* __restrict__ noise) {
    int qg = blockIdx.x >> 6;                  // 16 query groups of 1024
    int ms = blockIdx.x & 63;                  // 64 M-chunks of 64
    int p0 = qg * 1024 + threadIdx.x * CLQ_;
    int b  = p0 >> 13;
    const float4* PC = g_pc4 + b*M_;
    float qx[CLQ_], qy[CLQ_], qz[CLQ_], bd[CLQ_];
    int bi[CLQ_];
    #pragma unroll
    for (int q = 0; q < CLQ_; q++) {
        const float* np = noise + (size_t)(p0+q)*3;
        qx[q] = -2.f*np[0]; qy[q] = -2.f*np[1]; qz[q] = -2.f*np[2];
        bd[q] = FLT_MAX; bi[q] = 0;
    }
    int c0 = ms * 64;
    #pragma unroll 8
    for (int i = 0; i < 64; i++) {
        float4 c = __ldg(&PC[c0 + i]);
        #pragma unroll
        for (int q = 0; q < CLQ_; q++) {
            float d = fmaf(c.x, qx[q], fmaf(c.y, qy[q], fmaf(c.z, qz[q], c.w)));
            if (d < bd[q]) { bd[q] = d; bi[q] = c0 + i; }
        }
    }
    #pragma unroll
    for (int q = 0; q < CLQ_; q++) {
        unsigned u = __float_as_uint(bd[q]);
        u = (u & 0x80000000u) ? ~u : (u | 0x80000000u);   // order-preserving map
        unsigned long long key = ((unsigned long long)u << 32) | (unsigned)bi[q];
        atomicMin(&g_ckey[p0+q], key);
    }
}

// ---------------- 15-NN per clean point: warp-cooperative distributed top-K ----
__global__ void __launch_bounds__(512) k_knn() {
    extern __shared__ float4 sc[];                // 64 KB: whole batch cloud
    int blk  = blockIdx.x;                        // 512 blocks: 256/batch, 16 pts each
    int b    = blk >> 8;
    int w    = threadIdx.x >> 5;
    int lane = threadIdx.x & 31;
    int m    = (blk & 255) * 16 + w;
    const float4* PC = g_pc4 + b*M_;
    for (int i = threadIdx.x; i < M_; i += 512) sc[i] = PC[i];
    __syncthreads();
    float4 qc = sc[m];
    float qx = -2.f*qc.x, qy = -2.f*qc.y, qz = -2.f*qc.z;
    float Dl = FLT_MAX;                           // list entry held by this lane
    int   Il = -1;
    float worst = FLT_MAX;                        // warp-uniform 15th best
    for (int t0 = 0; t0 < M_; t0 += 32) {
        int c = t0 + lane;
        float4 cc = sc[c];
        float d = fmaf(cc.x, qx, fmaf(cc.y, qy, fmaf(cc.z, qz, cc.w)));
        bool pass = (d < worst) & (c != m);
        unsigned mask = __ballot_sync(0xffffffffu, pass);
        while (mask) {                            // warp-uniform loop
            int s = __ffs(mask) - 1;
            mask &= mask - 1;
            float bd = __shfl_sync(0xffffffffu, d, s);
            int   bix = t0 + s;
            if (bd < worst) {                     // warp-uniform condition
                float pd = __shfl_up_sync(0xffffffffu, Dl, 1);
                int   pi = __shfl_up_sync(0xffffffffu, Il, 1);
                if (lane == 0) { pd = -FLT_MAX; pi = -1; }
                if (lane < KNN_ && Dl >= bd) {
                    if (pd >= bd) { Dl = pd; Il = pi; }
                    else          { Dl = bd; Il = bix; }
                }
                worst = __shfl_sync(0xffffffffu, Dl, KNN_ - 1);
            }
        }
    }
    if (lane < KNN_) g_knn[(b*M_+m)*KNN_ + lane] = Il;
}

// ---------------- assemble: weights, weighted relu sums R, df[0:128] ----------------
__global__ void __launch_bounds__(256) k_assemble(const float* __restrict__ pcl,
                                                  const float* __restrict__ noise,
                                                  const float* __restrict__ feature) {
    int w = threadIdx.x >> 5, lane = threadIdx.x & 31;
    int p = blockIdx.x * 8 + w;           // warp per noisy point
    int b = p >> 13;                      // N = 8192
    int m0 = (int)(g_ckey[p] & 0xFFFFFFFFull);
    const float* PB = pcl + b*M_*3;
    const float* FB = feature + b*M_*C_;
    float nx = noise[p*3], ny = noise[p*3+1], nz = noise[p*3+2];
    float cx = PB[m0*3], cy = PB[m0*3+1], cz = PB[m0*3+2];
    float t[8], r[8];
    #pragma unroll
    for (int j = 0; j < 8; j++) {
        int c = lane + 32*j;
        const float* wv = g_w2as + c*6;
        t[j] = g_b2as[c] + wv[3]*cx + wv[4]*cy + wv[5]*cz
                         - (wv[0]*nx + wv[1]*ny + wv[2]*nz);
        r[j] = 0.f;
    }
    float S = 0.f, co0 = 0.f, co1 = 0.f;
    const int* nbp = g_knn + (b*M_+m0)*KNN_;
    #pragma unroll 1
    for (int k = 0; k < KNN_; k++) {
        int nb = nbp[k];
        float dx = PB[nb*3]-nx, dy = PB[nb*3+1]-ny, dz = PB[nb*3+2]-nz;
        float dst = sqrtf(fmaf(dx, dx, fmaf(dy, dy, dz*dz)));
        float e = __expf(-10.f * dst);
        S += e;
        const float* vr = g_v + (nb + b*M_)*HID_;
        #pragma unroll
        for (int j = 0; j < 8; j++) {
            float h = vr[lane + 32*j] + t[j];
            r[j] = fmaf(e, fmaxf(h, 0.f), r[j]);
        }
        co0 = fmaf(e, FB[nb*C_+lane],    co0);
        co1 = fmaf(e, FB[nb*C_+32+lane], co1);
    }
    float inv = 1.f / (S + 1e-7f);
    float* Rr = g_R + (size_t)p*HID_;
    #pragma unroll
    for (int j = 0; j < 8; j++) Rr[lane + 32*j] = r[j] * inv;
    float* dfp = g_DF + (size_t)p*128;
    dfp[lane]       = FB[m0*C_+lane];
    dfp[32+lane]    = FB[m0*C_+32+lane];
    dfp[64+lane]    = co0 * inv;
    dfp[96+lane]    = co1 * inv;
    if (lane == 0) g_sw[p] = S * inv;
}

// ---------------- fused GEMM, tf32 MMA stage1 + FFMA stage2 -------------------
// H1 = relu([DF|R](128x384) . Bcat(384x64) + b1as + sw*bb2); out = H1 . w1bT + b1b
// dyn smem: As[128][20] | Bh[16][72] | Bl[16][72] | H1T[64][136] | sws[128] | sb1[64] | sb2[64]
#define GS_AS   0
#define GS_BH   (128*20)
#define GS_BL   (GS_BH + 16*72)
#define GS_H1   (GS_BL + 16*72)
#define GS_SW   (GS_H1 + 64*136)
#define GS_B1   (GS_SW + 128)
#define GS_B2   (GS_B1 + 64)
#define GS_TOT  ((GS_B2 + 64) * 4)

__global__ void __launch_bounds__(256) k_gemm(const float* __restrict__ b1b,
                                              float* __restrict__ out) {
    extern __shared__ float sm[];
    float* As  = sm + GS_AS;
    float* Bh  = sm + GS_BH;
    float* Bl  = sm + GS_BL;
    float* H1T = sm + GS_H1;
    float* sws = sm + GS_SW;
    float* sb1 = sm + GS_B1;
    float* sb2 = sm + GS_B2;
    int tid = threadIdx.x;
    int p0 = blockIdx.x * 128;
    int wid = tid >> 5, lane = tid & 31;
    int lp = tid >> 1, kh = (tid & 1) * 8;
    int grp = lane >> 2, tig = lane & 3;

    if (tid < 128) sws[tid] = g_sw[p0 + tid];
    if (tid < 64)  { sb1[tid] = g_b1as[tid]; sb2[tid] = g_bb2[tid]; }

    float acc[32];
    #pragma unroll
    for (int i = 0; i < 32; i++) acc[i] = 0.f;

    for (int k0 = 0; k0 < 384; k0 += 16) {
        // stage A: rows p0..p0+127, k slice [k0, k0+16)
        const float* ap = (k0 < 128)
            ? g_DF + (size_t)(p0+lp)*128 + k0 + kh
            : g_R  + (size_t)(p0+lp)*HID_ + (k0 - 128) + kh;
        *(float4*)&As[lp*20 + kh]     = *(const float4*)ap;
        *(float4*)&As[lp*20 + kh + 4] = *(const float4*)(ap + 4);
        // stage B hi/lo: 16 x 64
        int bk = tid >> 4, bn = (tid & 15) * 4;
        *(float4*)&Bh[bk*72 + bn] = *(const float4*)(g_w1hi + (k0+bk)*C_ + bn);
        *(float4*)&Bl[bk*72 + bn] = *(const float4*)(g_w1lo + (k0+bk)*C_ + bn);
        __syncthreads();
        #pragma unroll
        for (int ks = 0; ks < 16; ks += 8) {
            // A fragment (m16 x k8) for rows [wid*16, wid*16+16)
            int r0 = wid*16 + grp, c0 = ks + tig;
            float af0 = As[r0*20 + c0];
            float af1 = As[(r0+8)*20 + c0];
            float af2 = As[r0*20 + c0 + 4];
            float af3 = As[(r0+8)*20 + c0 + 4];
            float h0 = tf32_hi(af0), h1 = tf32_hi(af1), h2 = tf32_hi(af2), h3 = tf32_hi(af3);
            uint32_t ah0 = __float_as_uint(h0), ah1 = __float_as_uint(h1);
            uint32_t ah2 = __float_as_uint(h2), ah3 = __float_as_uint(h3);
            uint32_t al0 = __float_as_uint(tf32_hi(af0 - h0));
            uint32_t al1 = __float_as_uint(tf32_hi(af1 - h1));
            uint32_t al2 = __float_as_uint(tf32_hi(af2 - h2));
            uint32_t al3 = __float_as_uint(tf32_hi(af3 - h3));
            #pragma unroll
            for (int nt = 0; nt < 8; nt++) {
                int bidx = (ks + tig)*72 + nt*8 + grp;
                uint32_t bh0 = __float_as_uint(Bh[bidx]);
                uint32_t bh1 = __float_as_uint(Bh[bidx + 4*72]);
                uint32_t bl0 = __float_as_uint(Bl[bidx]);
                uint32_t bl1 = __float_as_uint(Bl[bidx + 4*72]);
                float* d = acc + nt*4;
                mma_tf32(d, ah0, ah1, ah2, ah3, bh0, bh1);
                mma_tf32(d, ah0, ah1, ah2, ah3, bl0, bl1);
                mma_tf32(d, al0, al1, al2, al3, bh0, bh1);
            }
        }
        __syncthreads();
    }
    // epilogue stage 1: bias + sw*bb2, relu, transposed store to H1T[col][row]
    {
        int row = wid*16 + grp;
        float sw0 = sws[row], sw1 = sws[row+8];
        #pragma unroll
        for (int nt = 0; nt < 8; nt++) {
            int col = nt*8 + tig*2;
            float b0v = sb1[col]   + 0.f, c0v = sb2[col];
            float b1v = sb1[col+1],       c1v = sb2[col+1];
            float* d = acc + nt*4;
            H1T[col*136 + row]       = fmaxf(d[0] + b0v + sw0*c0v, 0.f);
            H1T[(col+1)*136 + row]   = fmaxf(d[1] + b1v + sw0*c1v, 0.f);
            H1T[col*136 + row + 8]   = fmaxf(d[2] + b0v + sw1*c0v, 0.f);
            H1T[(col+1)*136 + row+8] = fmaxf(d[3] + b1v + sw1*c1v, 0.f);
        }
    }
    __syncthreads();
    // stage 2: out = H1 . w1bT + b1b  (FFMA, K=64)
    int ty = tid >> 4, tx = tid & 15;
    float acc2[8][4];
    #pragma unroll
    for (int i = 0; i < 8; i++)
        #pragma unroll
        for (int j = 0; j < 4; j++) acc2[i][j] = 0.f;
    #pragma unroll 8
    for (int kc = 0; kc < 64; kc++) {
        float4 A0 = *(const float4*)&H1T[kc*136 + ty*8];
        float4 A1 = *(const float4*)&H1T[kc*136 + ty*8 + 4];
        float4 Bv = *(const float4*)(g_w1bT + kc*C_ + tx*4);
        float a[8] = {A0.x,A0.y,A0.z,A0.w,A1.x,A1.y,A1.z,A1.w};
        float bb[4] = {Bv.x,Bv.y,Bv.z,Bv.w};
        #pragma unroll
        for (int i = 0; i < 8; i++)
            #pragma unroll
            for (int j = 0; j < 4; j++)
                acc2[i][j] = fmaf(a[i], bb[j], acc2[i][j]);
    }
    #pragma unroll
    for (int i = 0; i < 8; i++) {
        float* dst = out + (size_t)(p0 + ty*8 + i)*C_ + tx*4;
        #pragma unroll
        for (int j = 0; j < 4; j++) dst[j] = acc2[i][j] + b1b[tx*4+j];
    }
}

// ---------------- launch ----------------
extern "C" void kernel_launch(void* const* d_in, const int* in_sizes, int n_in,
                              void* d_out, int out_size) {
    const float* pcl     = (const float*)d_in[0];
    const float* noise   = (const float*)d_in[1];
    const float* feature = (const float*)d_in[2];
    const float* w2a  = (const float*)d_in[3];
    const float* b2a  = (const float*)d_in[4];
    const float* g2a  = (const float*)d_in[5];
    const float* bt2a = (const float*)d_in[6];
    const float* w2b  = (const float*)d_in[7];
    const float* b2b  = (const float*)d_in[8];
    const float* w1a  = (const float*)d_in[9];
    const float* b1a  = (const float*)d_in[10];
    const float* g1a  = (const float*)d_in[11];
    const float* bt1a = (const float*)d_in[12];
    const float* w1b  = (const float*)d_in[13];
    const float* b1b  = (const float*)d_in[14];
    float* out = (float*)d_out;

    // one-time infra (first call is the non-captured correctness run)
    static cudaStream_t s1 = 0, s2 = 0;
    static cudaEvent_t  e0 = 0, e1 = 0, e2 = 0, e3 = 0;
    static bool infra_ok = false;
    static bool tried = false;
    if (!tried) {
        tried = true;
        infra_ok = (cudaStreamCreateWithFlags(&s1, cudaStreamNonBlocking) == cudaSuccess)
                && (cudaStreamCreateWithFlags(&s2, cudaStreamNonBlocking) == cudaSuccess)
                && (cudaEventCreateWithFlags(&e0, cudaEventDisableTiming) == cudaSuccess)
                && (cudaEventCreateWithFlags(&e1, cudaEventDisableTiming) == cudaSuccess)
                && (cudaEventCreateWithFlags(&e2, cudaEventDisableTiming) == cudaSuccess)
                && (cudaEventCreateWithFlags(&e3, cudaEventDisableTiming) == cudaSuccess);
        cudaFuncSetAttribute(k_knn, cudaFuncAttributeMaxDynamicSharedMemorySize, M_*16);
        cudaFuncSetAttribute(k_gemm, cudaFuncAttributeMaxDynamicSharedMemorySize, GS_TOT);
    }

    if (infra_ok) {
        // s2: prepw (no deps, needed only by gemm)
        cudaEventRecord(e0, 0);
        cudaStreamWaitEvent(s2, e0, 0);
        k_prepw<<<64, 256, 0, s2>>>(w2b, w1a, g1a, b2b);
        // s0: pc4, then fork knn to s1
        k_pc4<<<64, 256>>>(pcl);
        cudaEventRecord(e1, 0);
        cudaStreamWaitEvent(s1, e1, 0);
        k_knn<<<512, 512, M_*16, s1>>>();
        // s0 leg: close (no weight dep) + prep + vtab
        k_close<<<1024, 256>>>(noise);
        k_prep<<<17, 256>>>(w2a, b2a, g2a, bt2a, b1a, g1a, bt1a, w1b);
        k_vtab<<<(B_*M_*HID_)/256, 256>>>(pcl);
        // join knn before assemble
        cudaEventRecord(e2, s1);
        cudaStreamWaitEvent(0, e2, 0);
        k_assemble<<<2048, 256>>>(pcl, noise, feature);
        // join prepw before gemm
        cudaEventRecord(e3, s2);
        cudaStreamWaitEvent(0, e3, 0);
        k_gemm<<<128, 256, GS_TOT>>>(b1b, out);
    } else {
        k_prepw<<<64, 256>>>(w2b, w1a, g1a, b2b);
        k_pc4<<<64, 256>>>(pcl);
        k_knn<<<512, 512, M_*16>>>();
        k_close<<<1024, 256>>>(noise);
        k_prep<<<17, 256>>>(w2a, b2a, g2a, bt2a, b1a, g1a, bt1a, w1b);
        k_vtab<<<(B_*M_*HID_)/256, 256>>>(pcl);
        k_assemble<<<2048, 256>>>(pcl, noise, feature);
        k_gemm<<<128, 256, GS_TOT>>>(b1b, out);
    }
}